// round 2
// baseline (speedup 1.0000x reference)
#include <cuda_runtime.h>
#include <math.h>

// Problem constants
#define NN 50000
#define EE 800000

// ---------------- scratch (static device globals; no runtime allocation) ----------------
__device__ __align__(16) float g_h0[NN * 256];
__device__ __align__(16) float g_h[NN * 256];
__device__ __align__(16) float g_hp[NN * 256];
__device__ __align__(16) float g_ssrc[NN * 8];
__device__ __align__(16) float g_sdst[NN * 8];
__device__ __align__(16) float g_denom[NN * 8];
__device__ __align__(16) float g_accum[NN * 256];
__device__ __align__(16) float g_emb[3ll * NN * 256];
__device__ __align__(16) float g_t[NN * 128];
__device__ __align__(16) float g_scores[NN * 3];
__device__ __align__(16) float g_z[NN * 256];
__device__ __align__(16) float g_hcls[NN * 128];

// ---------------- generic tiled SGEMM: C = act(A[MxK] @ B[KxN] + bias) ----------------
// BM=BN=64, BK=16, 256 threads, 4x4 microtile per thread.
// Requires: K % 16 == 0, N % 64 == 0 (true for all calls: K in {128,256}, N in {128,256}).
__global__ void gemm_kernel(const float* __restrict__ A, const float* __restrict__ B,
                            const float* __restrict__ bias, float* __restrict__ C,
                            int M, int N, int K, int act)
{
    __shared__ float As[16][68];
    __shared__ float Bs[16][64];
    const int tid = threadIdx.x;
    const int tx = tid & 15, ty = tid >> 4;
    const int rowBase = blockIdx.y * 64;
    const int colBase = blockIdx.x * 64;

    float acc[4][4];
#pragma unroll
    for (int i = 0; i < 4; ++i)
#pragma unroll
        for (int j = 0; j < 4; ++j) acc[i][j] = 0.f;

    const int lr = tid >> 2;           // 0..63  (A row within tile)
    const int lk = (tid & 3) << 2;     // 0,4,8,12 (A k-offset, float4)
    const int brow = tid >> 4;         // 0..15  (B k row)
    const int bcol = (tid & 15) << 2;  // 0..60  (B col, float4)

    for (int k0 = 0; k0 < K; k0 += 16) {
        float4 a4 = make_float4(0.f, 0.f, 0.f, 0.f);
        int ar = rowBase + lr;
        if (ar < M) a4 = *(const float4*)(A + (size_t)ar * K + (k0 + lk));
        As[lk + 0][lr] = a4.x;
        As[lk + 1][lr] = a4.y;
        As[lk + 2][lr] = a4.z;
        As[lk + 3][lr] = a4.w;

        float4 b4 = *(const float4*)(B + (size_t)(k0 + brow) * N + (colBase + bcol));
        *(float4*)&Bs[brow][bcol] = b4;
        __syncthreads();

#pragma unroll
        for (int k = 0; k < 16; ++k) {
            float4 bv = *(const float4*)&Bs[k][tx << 2];
            float a0 = As[k][(ty << 2) + 0];
            float a1 = As[k][(ty << 2) + 1];
            float a2 = As[k][(ty << 2) + 2];
            float a3 = As[k][(ty << 2) + 3];
            acc[0][0] += a0 * bv.x; acc[0][1] += a0 * bv.y; acc[0][2] += a0 * bv.z; acc[0][3] += a0 * bv.w;
            acc[1][0] += a1 * bv.x; acc[1][1] += a1 * bv.y; acc[1][2] += a1 * bv.z; acc[1][3] += a1 * bv.w;
            acc[2][0] += a2 * bv.x; acc[2][1] += a2 * bv.y; acc[2][2] += a2 * bv.z; acc[2][3] += a2 * bv.w;
            acc[3][0] += a3 * bv.x; acc[3][1] += a3 * bv.y; acc[3][2] += a3 * bv.z; acc[3][3] += a3 * bv.w;
        }
        __syncthreads();
    }

#pragma unroll
    for (int i = 0; i < 4; ++i) {
        int r = rowBase + (ty << 2) + i;
        if (r >= M) continue;
        float o[4];
#pragma unroll
        for (int j = 0; j < 4; ++j) {
            int c = colBase + (tx << 2) + j;
            float v = acc[i][j] + (bias ? bias[c] : 0.f);
            if (act == 1) v = tanhf(v);
            else if (act == 2) v = fmaxf(v, 0.f);
            o[j] = v;
        }
        float4 ov = make_float4(o[0], o[1], o[2], o[3]);
        *(float4*)(C + (size_t)r * N + colBase + (tx << 2)) = ov;
    }
}

// ---------------- per-(node,head): attention logit halves + zero denom/accum ----------------
__global__ void prep_kernel(const float* __restrict__ hp,
                            const float* __restrict__ a_src, const float* __restrict__ a_dst,
                            float* __restrict__ s_src, float* __restrict__ s_dst,
                            float* __restrict__ denom, float* __restrict__ accum, int N)
{
    int t = blockIdx.x * blockDim.x + threadIdx.x;
    if (t >= N * 8) return;
    int n = t >> 3, h = t & 7;
    const float4* hv = (const float4*)(hp + (size_t)n * 256 + h * 32);
    const float4* av = (const float4*)(a_src + h * 32);
    const float4* bv = (const float4*)(a_dst + h * 32);
    float ss = 0.f, sd = 0.f;
#pragma unroll
    for (int i = 0; i < 8; ++i) {
        float4 x = hv[i], a = av[i], b = bv[i];
        ss += x.x * a.x + x.y * a.y + x.z * a.z + x.w * a.w;
        sd += x.x * b.x + x.y * b.y + x.z * b.z + x.w * b.w;
    }
    s_src[t] = ss;
    s_dst[t] = sd;
    denom[t] = 0.f;
    float4 z = make_float4(0.f, 0.f, 0.f, 0.f);
    float4* ac = (float4*)(accum + (size_t)n * 256 + h * 32);
#pragma unroll
    for (int i = 0; i < 8; ++i) ac[i] = z;
}

// Vector reduction (no return): red.global.add.v4.f32 (sm_90+)
__device__ __forceinline__ void red_add_f4(float* p, float4 v)
{
    asm volatile("red.global.add.v4.f32 [%0], {%1, %2, %3, %4};"
                 :: "l"(p), "f"(v.x), "f"(v.y), "f"(v.z), "f"(v.w) : "memory");
}

// ---------------- one warp per edge: ex = exp(leaky(s_src+s_dst)); accumulate num+denom ----------------
// Self-loops handled implicitly for edge ids in [E, E+N).
__global__ void edge_kernel(const int* __restrict__ esrc, const int* __restrict__ edst,
                            int E, int N,
                            const float* __restrict__ s_src, const float* __restrict__ s_dst,
                            const float* __restrict__ hp,
                            float* __restrict__ accum, float* __restrict__ denom)
{
    int gt = blockIdx.x * blockDim.x + threadIdx.x;
    int w = gt >> 5, lane = gt & 31;
    int Et = E + N;
    if (w >= Et) return;
    int s, d;
    if (w < E) { s = __ldg(esrc + w); d = __ldg(edst + w); }
    else       { s = d = w - E; }
    int h = lane >> 2;  // this lane's 8 floats all belong to head lane/4
    float e = __ldg(s_src + s * 8 + h) + __ldg(s_dst + d * 8 + h);
    e = (e > 0.f) ? e : 0.2f * e;           // leaky_relu(0.2)
    float ex = __expf(e);                    // max-subtraction skipped (ratio-invariant)
    if ((lane & 3) == 0)
        asm volatile("red.global.add.f32 [%0], %1;" :: "l"(denom + d * 8 + h), "f"(ex) : "memory");
    const float4* hv = (const float4*)(hp + (size_t)s * 256);
    float4 v0 = __ldg(hv + lane * 2), v1 = __ldg(hv + lane * 2 + 1);
    v0.x *= ex; v0.y *= ex; v0.z *= ex; v0.w *= ex;
    v1.x *= ex; v1.y *= ex; v1.z *= ex; v1.w *= ex;
    float* ac = accum + (size_t)d * 256;
    red_add_f4(ac + lane * 8, v0);
    red_add_f4(ac + lane * 8 + 4, v1);
}

// ---------------- normalize + bias + elu ----------------
__global__ void finalize_kernel(const float* __restrict__ accum, const float* __restrict__ denom,
                                const float* __restrict__ bias, float* __restrict__ out, int N)
{
    int t = blockIdx.x * blockDim.x + threadIdx.x;  // over N*64 float4s
    if (t >= N * 64) return;
    int n = t >> 6, q = t & 63;
    float inv = 1.f / denom[n * 8 + (q >> 3)];
    float4 v = *(const float4*)(accum + (size_t)n * 256 + q * 4);
    float4 b = *(const float4*)(bias + q * 4);
    float o[4] = { v.x * inv + b.x, v.y * inv + b.y, v.z * inv + b.z, v.w * inv + b.w };
#pragma unroll
    for (int i = 0; i < 4; ++i) o[i] = (o[i] > 0.f) ? o[i] : expm1f(o[i]);  // elu
    float4 ov = make_float4(o[0], o[1], o[2], o[3]);
    *(float4*)(out + (size_t)n * 256 + q * 4) = ov;
}

// ---------------- semantic score: scores[n,p] = t[n,:128] . W2 ----------------
__global__ void score_kernel(const float* __restrict__ t128, const float* __restrict__ W2,
                             float* __restrict__ scores, int N, int p)
{
    int gt = blockIdx.x * blockDim.x + threadIdx.x;
    int n = gt >> 5, lane = gt & 31;
    if (n >= N) return;
    const float* r = t128 + (size_t)n * 128;
    float v = r[lane] * W2[lane] + r[lane + 32] * W2[lane + 32]
            + r[lane + 64] * W2[lane + 64] + r[lane + 96] * W2[lane + 96];
#pragma unroll
    for (int o = 16; o > 0; o >>= 1) v += __shfl_xor_sync(0xffffffffu, v, o);
    if (lane == 0) scores[n * 3 + p] = v;
}

// ---------------- softmax over 3 metapaths + weighted sum ----------------
__global__ void combine_kernel(const float* __restrict__ e0, const float* __restrict__ e1,
                               const float* __restrict__ e2, const float* __restrict__ scores,
                               float* __restrict__ z, int N)
{
    int t = blockIdx.x * blockDim.x + threadIdx.x;
    if (t >= N * 64) return;
    int n = t >> 6, q = t & 63;
    float s0 = scores[n * 3], s1 = scores[n * 3 + 1], s2 = scores[n * 3 + 2];
    float m = fmaxf(s0, fmaxf(s1, s2));
    float w0 = __expf(s0 - m), w1 = __expf(s1 - m), w2 = __expf(s2 - m);
    float inv = 1.f / (w0 + w1 + w2);
    w0 *= inv; w1 *= inv; w2 *= inv;
    size_t off = (size_t)n * 256 + q * 4;
    float4 a = *(const float4*)(e0 + off);
    float4 b = *(const float4*)(e1 + off);
    float4 c = *(const float4*)(e2 + off);
    float4 o;
    o.x = w0 * a.x + w1 * b.x + w2 * c.x;
    o.y = w0 * a.y + w1 * b.y + w2 * c.y;
    o.z = w0 * a.z + w1 * b.z + w2 * c.z;
    o.w = w0 * a.w + w1 * b.w + w2 * c.w;
    *(float4*)(z + off) = o;
}

// ---------------- classifier head: logits[n,0:2] = hcls[n,:128] @ W2[128,2] + b2 ----------------
__global__ void logits_kernel(const float* __restrict__ hcls, const float* __restrict__ W2,
                              const float* __restrict__ b2, float* __restrict__ out, int N)
{
    int gt = blockIdx.x * blockDim.x + threadIdx.x;
    int n = gt >> 5, lane = gt & 31;
    if (n >= N) return;
    const float* r = hcls + (size_t)n * 128;
    float x0 = r[lane], x1 = r[lane + 32], x2 = r[lane + 64], x3 = r[lane + 96];
    float s0 = x0 * W2[lane * 2]           + x1 * W2[(lane + 32) * 2]
             + x2 * W2[(lane + 64) * 2]    + x3 * W2[(lane + 96) * 2];
    float s1 = x0 * W2[lane * 2 + 1]       + x1 * W2[(lane + 32) * 2 + 1]
             + x2 * W2[(lane + 64) * 2 + 1] + x3 * W2[(lane + 96) * 2 + 1];
#pragma unroll
    for (int o = 16; o > 0; o >>= 1) {
        s0 += __shfl_xor_sync(0xffffffffu, s0, o);
        s1 += __shfl_xor_sync(0xffffffffu, s1, o);
    }
    if (lane == 0) {
        out[n * 2]     = s0 + b2[0];
        out[n * 2 + 1] = s1 + b2[1];
    }
}

// ---------------- launch ----------------
extern "C" void kernel_launch(void* const* d_in, const int* in_sizes, int n_in,
                              void* d_out, int out_size)
{
    const float* x        = (const float*)d_in[0];
    const int*   edges    = (const int*)d_in[1];
    const float* proj_W   = (const float*)d_in[2];
    const float* proj_b   = (const float*)d_in[3];
    const float* gat_W    = (const float*)d_in[4];
    const float* gat_asrc = (const float*)d_in[5];
    const float* gat_adst = (const float*)d_in[6];
    const float* gat_b    = (const float*)d_in[7];
    const float* sem_W1   = (const float*)d_in[8];
    const float* sem_b1   = (const float*)d_in[9];
    const float* sem_W2   = (const float*)d_in[10];
    const float* cls_W1   = (const float*)d_in[11];
    const float* cls_b1   = (const float*)d_in[12];
    const float* cls_W2   = (const float*)d_in[13];
    const float* cls_b2   = (const float*)d_in[14];
    float* out = (float*)d_out;

    const int N = in_sizes[0] / 128;  // 50000
    const int E = in_sizes[1] / 6;    // 800000

    float *h0, *h, *hp, *ssrc, *sdst, *den, *acc, *emb, *tbuf, *scores, *z, *hcls;
    cudaGetSymbolAddress((void**)&h0,     g_h0);
    cudaGetSymbolAddress((void**)&h,      g_h);
    cudaGetSymbolAddress((void**)&hp,     g_hp);
    cudaGetSymbolAddress((void**)&ssrc,   g_ssrc);
    cudaGetSymbolAddress((void**)&sdst,   g_sdst);
    cudaGetSymbolAddress((void**)&den,    g_denom);
    cudaGetSymbolAddress((void**)&acc,    g_accum);
    cudaGetSymbolAddress((void**)&emb,    g_emb);
    cudaGetSymbolAddress((void**)&tbuf,   g_t);
    cudaGetSymbolAddress((void**)&scores, g_scores);
    cudaGetSymbolAddress((void**)&z,      g_z);
    cudaGetSymbolAddress((void**)&hcls,   g_hcls);

    // h0 = x @ proj_W + proj_b
    {
        dim3 grid(256 / 64, (N + 63) / 64);
        gemm_kernel<<<grid, 256>>>(x, proj_W, proj_b, h0, N, 256, 128, 0);
    }

    const int Et = E + N;
    for (int p = 0; p < 3; ++p) {
        const float* hcur = h0;
        for (int l = 0; l < 2; ++l) {
            const float* W    = gat_W    + (size_t)(p * 2 + l) * 256 * 256;
            const float* as_  = gat_asrc + (size_t)(p * 2 + l) * 256;
            const float* ad_  = gat_adst + (size_t)(p * 2 + l) * 256;
            const float* bb   = gat_b    + (size_t)(p * 2 + l) * 256;

            dim3 grid(256 / 64, (N + 63) / 64);
            gemm_kernel<<<grid, 256>>>(hcur, W, nullptr, hp, N, 256, 256, 0);
            prep_kernel<<<(N * 8 + 255) / 256, 256>>>(hp, as_, ad_, ssrc, sdst, den, acc, N);
            edge_kernel<<<(int)(((long long)Et * 32 + 255) / 256), 256>>>(
                edges + (size_t)p * 2 * E, edges + (size_t)p * 2 * E + E,
                E, N, ssrc, sdst, hp, acc, den);
            float* dst = (l == 0) ? h : (emb + (size_t)p * N * 256);
            finalize_kernel<<<(N * 64 + 255) / 256, 256>>>(acc, den, bb, dst, N);
            hcur = h;
        }
    }

    // semantic attention
    for (int p = 0; p < 3; ++p) {
        dim3 grid(128 / 64, (N + 63) / 64);
        gemm_kernel<<<grid, 256>>>(emb + (size_t)p * N * 256, sem_W1, sem_b1, tbuf, N, 128, 256, 1);
        score_kernel<<<(N * 32 + 255) / 256, 256>>>(tbuf, sem_W2, scores, N, p);
    }
    combine_kernel<<<(N * 64 + 255) / 256, 256>>>(
        emb, emb + (size_t)N * 256, emb + (size_t)2 * N * 256, scores, z, N);

    // classifier
    {
        dim3 grid(128 / 64, (N + 63) / 64);
        gemm_kernel<<<grid, 256>>>(z, cls_W1, cls_b1, hcls, N, 128, 256, 2);
    }
    logits_kernel<<<(N * 32 + 255) / 256, 256>>>(hcls, cls_W2, cls_b2, out, N);
}

// round 4
// speedup vs baseline: 1.5233x; 1.5233x over previous
#include <cuda_runtime.h>
#include <math.h>

#define NN 50000
#define EE 800000

// ---------------- scratch ----------------
__device__ __align__(16) float g_h0[NN * 256];
__device__ __align__(16) float g_h[NN * 256];
__device__ __align__(16) float g_hp[NN * 256];
__device__ __align__(16) float g_ssrc[NN * 8];
__device__ __align__(16) float g_sdst[NN * 8];
__device__ __align__(16) float g_emb[3ll * NN * 256];
__device__ __align__(16) float g_t[NN * 128];
__device__ __align__(16) float g_scores[NN * 3];
__device__ __align__(16) float g_z[NN * 256];
__device__ __align__(16) float g_hcls[NN * 128];
// CSR scratch (rebuilt per metapath, reused across the 2 layers)
__device__ int g_deg[NN];
__device__ int g_off[NN + 1];
__device__ int g_cursor[NN];
__device__ int g_csr[EE + NN];

// ---------------- SGEMM: C = act(A[MxK] @ B[KxN] + bias) ----------------
// BM=128, BN=64, BK=16, 256 threads, 8x4 microtile.
__global__ void gemm_kernel(const float* __restrict__ A, const float* __restrict__ B,
                            const float* __restrict__ bias, float* __restrict__ C,
                            int M, int N, int K, int act)
{
    __shared__ float As[16][128];
    __shared__ float Bs[16][64];
    const int tid = threadIdx.x;
    const int tx = tid & 15, ty = tid >> 4;
    const int rowBase = blockIdx.y * 128;
    const int colBase = blockIdx.x * 64;

    float acc[8][4];
#pragma unroll
    for (int i = 0; i < 8; ++i)
#pragma unroll
        for (int j = 0; j < 4; ++j) acc[i][j] = 0.f;

    const int alr = tid >> 2;           // 0..63
    const int akq = (tid & 3) << 2;     // 0,4,8,12
    const int brow = tid >> 4;          // 0..15
    const int bcol = (tid & 15) << 2;   // 0..60

    for (int k0 = 0; k0 < K; k0 += 16) {
#pragma unroll
        for (int h = 0; h < 2; ++h) {
            int r = alr + h * 64;
            int gr = rowBase + r;
            float4 a4 = make_float4(0.f, 0.f, 0.f, 0.f);
            if (gr < M) a4 = *(const float4*)(A + (size_t)gr * K + k0 + akq);
            As[akq + 0][r] = a4.x;
            As[akq + 1][r] = a4.y;
            As[akq + 2][r] = a4.z;
            As[akq + 3][r] = a4.w;
        }
        *(float4*)&Bs[brow][bcol] = *(const float4*)(B + (size_t)(k0 + brow) * N + colBase + bcol);
        __syncthreads();

#pragma unroll
        for (int k = 0; k < 16; ++k) {
            float4 bv = *(const float4*)&Bs[k][tx << 2];
            float4 a0 = *(const float4*)&As[k][ty << 3];
            float4 a1 = *(const float4*)&As[k][(ty << 3) + 4];
            float av[8] = {a0.x, a0.y, a0.z, a0.w, a1.x, a1.y, a1.z, a1.w};
#pragma unroll
            for (int i = 0; i < 8; ++i) {
                acc[i][0] += av[i] * bv.x;
                acc[i][1] += av[i] * bv.y;
                acc[i][2] += av[i] * bv.z;
                acc[i][3] += av[i] * bv.w;
            }
        }
        __syncthreads();
    }

#pragma unroll
    for (int i = 0; i < 8; ++i) {
        int r = rowBase + (ty << 3) + i;
        if (r >= M) continue;
        float o[4];
#pragma unroll
        for (int j = 0; j < 4; ++j) {
            int c = colBase + (tx << 2) + j;
            float v = acc[i][j] + (bias ? bias[c] : 0.f);
            if (act == 1) v = tanhf(v);
            else if (act == 2) v = fmaxf(v, 0.f);
            o[j] = v;
        }
        *(float4*)(C + (size_t)r * N + colBase + (tx << 2)) = make_float4(o[0], o[1], o[2], o[3]);
    }
}

// ---------------- CSR build ----------------
__global__ void deg_init_kernel(int* __restrict__ deg, int N)
{
    int t = blockIdx.x * blockDim.x + threadIdx.x;
    if (t < N) deg[t] = 1;  // self-loop
}

__global__ void deg_count_kernel(const int* __restrict__ edst, int* __restrict__ deg, int E)
{
    int t = blockIdx.x * blockDim.x + threadIdx.x;
    if (t < E) atomicAdd(deg + __ldg(edst + t), 1);
}

// single block, 1024 threads: exclusive scan deg -> off, off[N] = total
__global__ void scan_kernel(const int* __restrict__ deg, int* __restrict__ off, int N)
{
    __shared__ int part[1024];
    int tid = threadIdx.x;
    int per = (N + 1023) >> 10;
    int beg = tid * per, end = min(beg + per, N);
    int s = 0;
    for (int i = beg; i < end; ++i) s += deg[i];
    part[tid] = s;
    __syncthreads();
    for (int o = 1; o < 1024; o <<= 1) {
        int v = (tid >= o) ? part[tid - o] : 0;
        __syncthreads();
        part[tid] += v;
        __syncthreads();
    }
    int pre = (tid > 0) ? part[tid - 1] : 0;
    for (int i = beg; i < end; ++i) { off[i] = pre; pre += deg[i]; }
    if (tid == 1023) off[N] = pre;
}

// place self-loop first in each segment, set fill cursor past it
__global__ void csr_init_kernel(const int* __restrict__ off, int* __restrict__ cursor,
                                int* __restrict__ csr, int N)
{
    int t = blockIdx.x * blockDim.x + threadIdx.x;
    if (t >= N) return;
    int o = off[t];
    csr[o] = t;
    cursor[t] = o + 1;
}

__global__ void csr_fill_kernel(const int* __restrict__ esrc, const int* __restrict__ edst,
                                int* __restrict__ cursor, int* __restrict__ csr, int E)
{
    int t = blockIdx.x * blockDim.x + threadIdx.x;
    if (t >= E) return;
    int d = __ldg(edst + t);
    int pos = atomicAdd(cursor + d, 1);
    csr[pos] = __ldg(esrc + t);
}

// ---------------- per-(node,head): attention logit halves ----------------
__global__ void prep_kernel(const float* __restrict__ hp,
                            const float* __restrict__ a_src, const float* __restrict__ a_dst,
                            float* __restrict__ s_src, float* __restrict__ s_dst, int N)
{
    int t = blockIdx.x * blockDim.x + threadIdx.x;
    if (t >= N * 8) return;
    int n = t >> 3, h = t & 7;
    const float4* hv = (const float4*)(hp + (size_t)n * 256 + h * 32);
    const float4* av = (const float4*)(a_src + h * 32);
    const float4* bv = (const float4*)(a_dst + h * 32);
    float ss = 0.f, sd = 0.f;
#pragma unroll
    for (int i = 0; i < 8; ++i) {
        float4 x = hv[i], a = av[i], b = bv[i];
        ss += x.x * a.x + x.y * a.y + x.z * a.z + x.w * a.w;
        sd += x.x * b.x + x.y * b.y + x.z * b.z + x.w * b.w;
    }
    s_src[t] = ss;
    s_dst[t] = sd;
}

// ---------------- warp-per-node gather aggregation (softmax fused, finalize fused) ----------------
// lane handles floats [lane*8, lane*8+8) of the 256-d output; head = lane/4.
__global__ void aggregate_kernel(const int* __restrict__ off, const int* __restrict__ csr,
                                 const float* __restrict__ s_src, const float* __restrict__ s_dst,
                                 const float* __restrict__ hp, const float* __restrict__ bias,
                                 float* __restrict__ out, int N)
{
    int gt = blockIdx.x * blockDim.x + threadIdx.x;
    int w = gt >> 5, lane = gt & 31;
    if (w >= N) return;
    int beg = __ldg(off + w), end = __ldg(off + w + 1);
    int h = lane >> 2;
    float sd = __ldg(s_dst + w * 8 + h);

    float4 acc0 = make_float4(0.f, 0.f, 0.f, 0.f);
    float4 acc1 = make_float4(0.f, 0.f, 0.f, 0.f);
    float den = 0.f;

    for (int e = beg; e < end; ++e) {
        int s = __ldg(csr + e);
        float ee = __ldg(s_src + s * 8 + h) + sd;
        ee = (ee > 0.f) ? ee : 0.2f * ee;     // leaky_relu(0.2)
        float ex = __expf(ee);                 // max-shift skipped (ratio-invariant)
        den += ex;
        const float4* hv = (const float4*)(hp + (size_t)s * 256);
        float4 v0 = __ldg(hv + lane * 2), v1 = __ldg(hv + lane * 2 + 1);
        acc0.x += ex * v0.x; acc0.y += ex * v0.y; acc0.z += ex * v0.z; acc0.w += ex * v0.w;
        acc1.x += ex * v1.x; acc1.y += ex * v1.y; acc1.z += ex * v1.z; acc1.w += ex * v1.w;
    }
    float inv = 1.f / den;
    const float4* bb = (const float4*)(bias + lane * 8);
    float4 b0 = bb[0], b1 = bb[1];
    float o[8] = { acc0.x * inv + b0.x, acc0.y * inv + b0.y, acc0.z * inv + b0.z, acc0.w * inv + b0.w,
                   acc1.x * inv + b1.x, acc1.y * inv + b1.y, acc1.z * inv + b1.z, acc1.w * inv + b1.w };
#pragma unroll
    for (int i = 0; i < 8; ++i) o[i] = (o[i] > 0.f) ? o[i] : expm1f(o[i]);  // elu
    float4* ov = (float4*)(out + (size_t)w * 256 + lane * 8);
    ov[0] = make_float4(o[0], o[1], o[2], o[3]);
    ov[1] = make_float4(o[4], o[5], o[6], o[7]);
}

// ---------------- semantic score ----------------
__global__ void score_kernel(const float* __restrict__ t128, const float* __restrict__ W2,
                             float* __restrict__ scores, int N, int p)
{
    int gt = blockIdx.x * blockDim.x + threadIdx.x;
    int n = gt >> 5, lane = gt & 31;
    if (n >= N) return;
    const float* r = t128 + (size_t)n * 128;
    float v = r[lane] * W2[lane] + r[lane + 32] * W2[lane + 32]
            + r[lane + 64] * W2[lane + 64] + r[lane + 96] * W2[lane + 96];
#pragma unroll
    for (int o = 16; o > 0; o >>= 1) v += __shfl_xor_sync(0xffffffffu, v, o);
    if (lane == 0) scores[n * 3 + p] = v;
}

// ---------------- softmax over 3 metapaths + weighted sum ----------------
__global__ void combine_kernel(const float* __restrict__ e0, const float* __restrict__ e1,
                               const float* __restrict__ e2, const float* __restrict__ scores,
                               float* __restrict__ z, int N)
{
    int t = blockIdx.x * blockDim.x + threadIdx.x;
    if (t >= N * 64) return;
    int n = t >> 6, q = t & 63;
    float s0 = scores[n * 3], s1 = scores[n * 3 + 1], s2 = scores[n * 3 + 2];
    float m = fmaxf(s0, fmaxf(s1, s2));
    float w0 = __expf(s0 - m), w1 = __expf(s1 - m), w2 = __expf(s2 - m);
    float inv = 1.f / (w0 + w1 + w2);
    w0 *= inv; w1 *= inv; w2 *= inv;
    size_t offi = (size_t)n * 256 + q * 4;
    float4 a = *(const float4*)(e0 + offi);
    float4 b = *(const float4*)(e1 + offi);
    float4 c = *(const float4*)(e2 + offi);
    float4 o;
    o.x = w0 * a.x + w1 * b.x + w2 * c.x;
    o.y = w0 * a.y + w1 * b.y + w2 * c.y;
    o.z = w0 * a.z + w1 * b.z + w2 * c.z;
    o.w = w0 * a.w + w1 * b.w + w2 * c.w;
    *(float4*)(z + offi) = o;
}

// ---------------- classifier head ----------------
__global__ void logits_kernel(const float* __restrict__ hcls, const float* __restrict__ W2,
                              const float* __restrict__ b2, float* __restrict__ out, int N)
{
    int gt = blockIdx.x * blockDim.x + threadIdx.x;
    int n = gt >> 5, lane = gt & 31;
    if (n >= N) return;
    const float* r = hcls + (size_t)n * 128;
    float x0 = r[lane], x1 = r[lane + 32], x2 = r[lane + 64], x3 = r[lane + 96];
    float s0 = x0 * W2[lane * 2]            + x1 * W2[(lane + 32) * 2]
             + x2 * W2[(lane + 64) * 2]     + x3 * W2[(lane + 96) * 2];
    float s1 = x0 * W2[lane * 2 + 1]        + x1 * W2[(lane + 32) * 2 + 1]
             + x2 * W2[(lane + 64) * 2 + 1] + x3 * W2[(lane + 96) * 2 + 1];
#pragma unroll
    for (int o = 16; o > 0; o >>= 1) {
        s0 += __shfl_xor_sync(0xffffffffu, s0, o);
        s1 += __shfl_xor_sync(0xffffffffu, s1, o);
    }
    if (lane == 0) {
        out[n * 2]     = s0 + b2[0];
        out[n * 2 + 1] = s1 + b2[1];
    }
}

// ---------------- launch ----------------
extern "C" void kernel_launch(void* const* d_in, const int* in_sizes, int n_in,
                              void* d_out, int out_size)
{
    const float* x        = (const float*)d_in[0];
    const int*   edges    = (const int*)d_in[1];
    const float* proj_W   = (const float*)d_in[2];
    const float* proj_b   = (const float*)d_in[3];
    const float* gat_W    = (const float*)d_in[4];
    const float* gat_asrc = (const float*)d_in[5];
    const float* gat_adst = (const float*)d_in[6];
    const float* gat_b    = (const float*)d_in[7];
    const float* sem_W1   = (const float*)d_in[8];
    const float* sem_b1   = (const float*)d_in[9];
    const float* sem_W2   = (const float*)d_in[10];
    const float* cls_W1   = (const float*)d_in[11];
    const float* cls_b1   = (const float*)d_in[12];
    const float* cls_W2   = (const float*)d_in[13];
    const float* cls_b2   = (const float*)d_in[14];
    float* out = (float*)d_out;

    const int N = in_sizes[0] / 128;  // 50000
    const int E = in_sizes[1] / 6;    // 800000

    float *h0, *h, *hp, *ssrc, *sdst, *emb, *tbuf, *scores, *z, *hcls;
    int *deg, *off, *cursor, *csr;
    cudaGetSymbolAddress((void**)&h0,     g_h0);
    cudaGetSymbolAddress((void**)&h,      g_h);
    cudaGetSymbolAddress((void**)&hp,     g_hp);
    cudaGetSymbolAddress((void**)&ssrc,   g_ssrc);
    cudaGetSymbolAddress((void**)&sdst,   g_sdst);
    cudaGetSymbolAddress((void**)&emb,    g_emb);
    cudaGetSymbolAddress((void**)&tbuf,   g_t);
    cudaGetSymbolAddress((void**)&scores, g_scores);
    cudaGetSymbolAddress((void**)&z,      g_z);
    cudaGetSymbolAddress((void**)&hcls,   g_hcls);
    cudaGetSymbolAddress((void**)&deg,    g_deg);
    cudaGetSymbolAddress((void**)&off,    g_off);
    cudaGetSymbolAddress((void**)&cursor, g_cursor);
    cudaGetSymbolAddress((void**)&csr,    g_csr);

    // h0 = x @ proj_W + proj_b
    {
        dim3 grid(256 / 64, (N + 127) / 128);
        gemm_kernel<<<grid, 256>>>(x, proj_W, proj_b, h0, N, 256, 128, 0);
    }

    for (int p = 0; p < 3; ++p) {
        const int* esrc = edges + (size_t)p * 2 * E;
        const int* edst = esrc + E;
        // Build dst-CSR (with self-loops) — reused by both layers
        deg_init_kernel<<<(N + 255) / 256, 256>>>(deg, N);
        deg_count_kernel<<<(E + 255) / 256, 256>>>(edst, deg, E);
        scan_kernel<<<1, 1024>>>(deg, off, N);
        csr_init_kernel<<<(N + 255) / 256, 256>>>(off, cursor, csr, N);
        csr_fill_kernel<<<(E + 255) / 256, 256>>>(esrc, edst, cursor, csr, E);

        const float* hcur = h0;
        for (int l = 0; l < 2; ++l) {
            const float* W   = gat_W    + (size_t)(p * 2 + l) * 256 * 256;
            const float* as_ = gat_asrc + (size_t)(p * 2 + l) * 256;
            const float* ad_ = gat_adst + (size_t)(p * 2 + l) * 256;
            const float* bb  = gat_b    + (size_t)(p * 2 + l) * 256;

            dim3 grid(256 / 64, (N + 127) / 128);
            gemm_kernel<<<grid, 256>>>(hcur, W, nullptr, hp, N, 256, 256, 0);
            prep_kernel<<<(N * 8 + 255) / 256, 256>>>(hp, as_, ad_, ssrc, sdst, N);
            float* dst = (l == 0) ? h : (emb + (size_t)p * N * 256);
            aggregate_kernel<<<(N * 32 + 255) / 256, 256>>>(off, csr, ssrc, sdst, hp, bb, dst, N);
            hcur = h;
        }
    }

    // semantic attention
    for (int p = 0; p < 3; ++p) {
        dim3 grid(128 / 64, (N + 127) / 128);
        gemm_kernel<<<grid, 256>>>(emb + (size_t)p * N * 256, sem_W1, sem_b1, tbuf, N, 128, 256, 1);
        score_kernel<<<(N * 32 + 255) / 256, 256>>>(tbuf, sem_W2, scores, N, p);
    }
    combine_kernel<<<(N * 64 + 255) / 256, 256>>>(
        emb, emb + (size_t)N * 256, emb + (size_t)2 * N * 256, scores, z, N);

    // classifier
    {
        dim3 grid(128 / 64, (N + 127) / 128);
        gemm_kernel<<<grid, 256>>>(z, cls_W1, cls_b1, hcls, N, 128, 256, 2);
    }
    logits_kernel<<<(N * 32 + 255) / 256, 256>>>(hcls, cls_W2, cls_b2, out, N);
}

// round 7
// speedup vs baseline: 2.0035x; 1.3152x over previous
#include <cuda_runtime.h>
#include <cuda_bf16.h>
#include <math.h>

#define NN 50000
#define EE 800000

// ---------------- scratch ----------------
__device__ __align__(16) float g_h0[NN * 256];
__device__ __align__(16) float g_h[NN * 256];
__device__ __align__(16) float g_hp[NN * 256];
__device__ __align__(16) float g_ssrc[NN * 8];
__device__ __align__(16) float g_sdst[NN * 8];
__device__ __align__(16) float g_emb[3ll * NN * 256];
__device__ __align__(16) float g_t[NN * 128];
__device__ __align__(16) float g_scores[NN * 3];
__device__ __align__(16) float g_z[NN * 256];
__device__ __align__(16) float g_hcls[NN * 128];
// CSR scratch
__device__ int g_deg[NN];
__device__ int g_off[NN + 1];
__device__ int g_cursor[NN];
__device__ int g_csr[EE + NN];
__device__ int g_partials[64];

// ---------------- bf16 split helpers ----------------
__device__ __forceinline__ void split2(float a, float b, unsigned& hi, unsigned& lo)
{
    __nv_bfloat16 ah = __float2bfloat16_rn(a);
    __nv_bfloat16 bh = __float2bfloat16_rn(b);
    __nv_bfloat16 al = __float2bfloat16_rn(a - __bfloat162float(ah));
    __nv_bfloat16 bl = __float2bfloat16_rn(b - __bfloat162float(bh));
    __nv_bfloat162 h2 = __halves2bfloat162(ah, bh);
    __nv_bfloat162 l2 = __halves2bfloat162(al, bl);
    hi = *reinterpret_cast<unsigned*>(&h2);
    lo = *reinterpret_cast<unsigned*>(&l2);
}

__device__ __forceinline__ void mma_bf16(float (&d)[4], const unsigned (&a)[4], const unsigned (&b)[2])
{
    asm volatile("mma.sync.aligned.m16n8k16.row.col.f32.bf16.bf16.f32 "
        "{%0,%1,%2,%3}, {%4,%5,%6,%7}, {%8,%9}, {%0,%1,%2,%3};"
        : "+f"(d[0]), "+f"(d[1]), "+f"(d[2]), "+f"(d[3])
        : "r"(a[0]), "r"(a[1]), "r"(a[2]), "r"(a[3]), "r"(b[0]), "r"(b[1]));
}

// ---------------- bf16x3 tensor-core GEMM: C = act(A[MxK] @ B[KxN] + bias) ----------------
// BM=128, BN=64, BK=16. 256 threads = 8 warps (4m x 2n), warp tile 32x32 via m16n8k16.
// Requires K % 16 == 0, N % 64 == 0.
__global__ void gemm_kernel(const float* __restrict__ A, const float* __restrict__ B,
                            const float* __restrict__ bias, float* __restrict__ C,
                            int M, int N, int K, int act)
{
    __shared__ unsigned AsH[128][12], AsL[128][12];   // [m][k-pair], pad 12 (conflict-free frag loads)
    __shared__ unsigned BsH[64][12],  BsL[64][12];    // [n][k-pair]

    const int tid = threadIdx.x;
    const int lane = tid & 31;
    const int warp = tid >> 5;
    const int wm = warp & 3, wn = warp >> 2;
    const int rowBase = blockIdx.y * 128;
    const int colBase = blockIdx.x * 64;
    const int g = lane >> 2, t = lane & 3;

    float acc[2][4][4];
#pragma unroll
    for (int mt = 0; mt < 2; ++mt)
#pragma unroll
        for (int nt = 0; nt < 4; ++nt)
#pragma unroll
            for (int i = 0; i < 4; ++i) acc[mt][nt][i] = 0.f;

    // loader indices
    const int am = tid >> 1;            // 0..127 (A row in tile)
    const int ak = (tid & 1) * 8;       // 0 or 8 (k offset in floats)
    const int bn = tid & 63;            // 0..63 (B col in tile)
    const int bk2 = tid >> 6;           // 0..3 (k-pair index base)

    for (int k0 = 0; k0 < K; k0 += 16) {
        // load + split A (128x16)
        {
            int gr = rowBase + am;
            float4 f0 = make_float4(0.f, 0.f, 0.f, 0.f);
            float4 f1 = make_float4(0.f, 0.f, 0.f, 0.f);
            if (gr < M) {
                const float* ap = A + (size_t)gr * K + k0 + ak;
                f0 = *(const float4*)ap;
                f1 = *(const float4*)(ap + 4);
            }
            int kp = ak >> 1;
            unsigned h, l;
            split2(f0.x, f0.y, h, l); AsH[am][kp + 0] = h; AsL[am][kp + 0] = l;
            split2(f0.z, f0.w, h, l); AsH[am][kp + 1] = h; AsL[am][kp + 1] = l;
            split2(f1.x, f1.y, h, l); AsH[am][kp + 2] = h; AsL[am][kp + 2] = l;
            split2(f1.z, f1.w, h, l); AsH[am][kp + 3] = h; AsL[am][kp + 3] = l;
        }
        // load + split B (16x64), store transposed [n][kpair]
        {
#pragma unroll
            for (int r = 0; r < 2; ++r) {
                int kp = bk2 + r * 4;
                const float* bp = B + (size_t)(k0 + 2 * kp) * N + colBase + bn;
                float x = bp[0];
                float y = bp[N];
                unsigned h, l;
                split2(x, y, h, l);
                BsH[bn][kp] = h; BsL[bn][kp] = l;
            }
        }
        __syncthreads();

        unsigned aH[2][4], aL[2][4], bH[4][2], bL[4][2];
#pragma unroll
        for (int mt = 0; mt < 2; ++mt) {
            int mr = wm * 32 + mt * 16;
            aH[mt][0] = AsH[mr + g][t];     aH[mt][1] = AsH[mr + 8 + g][t];
            aH[mt][2] = AsH[mr + g][t + 4]; aH[mt][3] = AsH[mr + 8 + g][t + 4];
            aL[mt][0] = AsL[mr + g][t];     aL[mt][1] = AsL[mr + 8 + g][t];
            aL[mt][2] = AsL[mr + g][t + 4]; aL[mt][3] = AsL[mr + 8 + g][t + 4];
        }
#pragma unroll
        for (int nt = 0; nt < 4; ++nt) {
            int nr = wn * 32 + nt * 8;
            bH[nt][0] = BsH[nr + g][t]; bH[nt][1] = BsH[nr + g][t + 4];
            bL[nt][0] = BsL[nr + g][t]; bL[nt][1] = BsL[nr + g][t + 4];
        }
#pragma unroll
        for (int mt = 0; mt < 2; ++mt)
#pragma unroll
            for (int nt = 0; nt < 4; ++nt) {
                mma_bf16(acc[mt][nt], aH[mt], bH[nt]);  // hi*hi
                mma_bf16(acc[mt][nt], aL[mt], bH[nt]);  // lo*hi
                mma_bf16(acc[mt][nt], aH[mt], bL[nt]);  // hi*lo
            }
        __syncthreads();
    }

    // epilogue
#pragma unroll
    for (int mt = 0; mt < 2; ++mt) {
#pragma unroll
        for (int nt = 0; nt < 4; ++nt) {
            int c = colBase + wn * 32 + nt * 8 + 2 * t;
            float b0 = bias ? bias[c] : 0.f;
            float b1 = bias ? bias[c + 1] : 0.f;
#pragma unroll
            for (int half = 0; half < 2; ++half) {
                int r = rowBase + wm * 32 + mt * 16 + g + half * 8;
                if (r >= M) continue;
                float v0 = acc[mt][nt][half * 2 + 0] + b0;
                float v1 = acc[mt][nt][half * 2 + 1] + b1;
                if (act == 1) { v0 = tanhf(v0); v1 = tanhf(v1); }
                else if (act == 2) { v0 = fmaxf(v0, 0.f); v1 = fmaxf(v1, 0.f); }
                *(float2*)(C + (size_t)r * N + c) = make_float2(v0, v1);
            }
        }
    }
}

// ---------------- CSR build ----------------
__global__ void deg_init_kernel(int* __restrict__ deg, int N)
{
    int t = blockIdx.x * blockDim.x + threadIdx.x;
    if (t < N) deg[t] = 1;  // self-loop
}

__global__ void deg_count_kernel(const int* __restrict__ edst, int* __restrict__ deg, int E)
{
    int t = blockIdx.x * blockDim.x + threadIdx.x;
    if (t < E) atomicAdd(deg + __ldg(edst + t), 1);
}

// multi-block scan: local exclusive scans + per-block totals
__global__ void scan_local_kernel(const int* __restrict__ deg, int* __restrict__ off,
                                  int* __restrict__ partials, int N)
{
    __shared__ int sm[1024];
    int b = blockIdx.x, tid = threadIdx.x;
    int i = b * 1024 + tid;
    int v = (i < N) ? deg[i] : 0;
    sm[tid] = v;
    __syncthreads();
    for (int o = 1; o < 1024; o <<= 1) {
        int x = (tid >= o) ? sm[tid - o] : 0;
        __syncthreads();
        sm[tid] += x;
        __syncthreads();
    }
    if (i < N) off[i] = sm[tid] - v;   // exclusive
    if (tid == 1023) partials[b] = sm[1023];
}

// 1 block of 64 threads: exclusive scan of up to 64 partials; writes off[N] = grand total
__global__ void scan_partials_kernel(int* __restrict__ partials, int nb,
                                     int* __restrict__ off, int N)
{
    __shared__ int sm[64];
    int tid = threadIdx.x;
    int v = (tid < nb) ? partials[tid] : 0;
    sm[tid] = v;
    __syncthreads();
    for (int o = 1; o < 64; o <<= 1) {
        int x = (tid >= o) ? sm[tid - o] : 0;
        __syncthreads();
        sm[tid] += x;
        __syncthreads();
    }
    if (tid < nb) partials[tid] = sm[tid] - v;   // exclusive
    if (tid == 63) off[N] = sm[63];
}

__global__ void scan_add_kernel(int* __restrict__ off, const int* __restrict__ partials, int N)
{
    int i = blockIdx.x * blockDim.x + threadIdx.x;
    if (i < N) off[i] += partials[blockIdx.x >> 2];  // 256 threads/block -> 4 blocks per 1024-chunk
}

// place self-loop first in each segment, set fill cursor past it
__global__ void csr_init_kernel(const int* __restrict__ off, int* __restrict__ cursor,
                                int* __restrict__ csr, int N)
{
    int t = blockIdx.x * blockDim.x + threadIdx.x;
    if (t >= N) return;
    int o = off[t];
    csr[o] = t;
    cursor[t] = o + 1;
}

__global__ void csr_fill_kernel(const int* __restrict__ esrc, const int* __restrict__ edst,
                                int* __restrict__ cursor, int* __restrict__ csr, int E)
{
    int t = blockIdx.x * blockDim.x + threadIdx.x;
    if (t >= E) return;
    int d = __ldg(edst + t);
    int pos = atomicAdd(cursor + d, 1);
    csr[pos] = __ldg(esrc + t);
}

// ---------------- per-(node,head): attention logit halves ----------------
__global__ void prep_kernel(const float* __restrict__ hp,
                            const float* __restrict__ a_src, const float* __restrict__ a_dst,
                            float* __restrict__ s_src, float* __restrict__ s_dst, int N)
{
    int t = blockIdx.x * blockDim.x + threadIdx.x;
    if (t >= N * 8) return;
    int n = t >> 3, h = t & 7;
    const float4* hv = (const float4*)(hp + (size_t)n * 256 + h * 32);
    const float4* av = (const float4*)(a_src + h * 32);
    const float4* bv = (const float4*)(a_dst + h * 32);
    float ss = 0.f, sd = 0.f;
#pragma unroll
    for (int i = 0; i < 8; ++i) {
        float4 x = hv[i], a = av[i], b = bv[i];
        ss += x.x * a.x + x.y * a.y + x.z * a.z + x.w * a.w;
        sd += x.x * b.x + x.y * b.y + x.z * b.z + x.w * b.w;
    }
    s_src[t] = ss;
    s_dst[t] = sd;
}

// ---------------- warp-per-node gather aggregation (softmax+finalize fused, unroll-2) ----------------
__global__ void aggregate_kernel(const int* __restrict__ off, const int* __restrict__ csr,
                                 const float* __restrict__ s_src, const float* __restrict__ s_dst,
                                 const float* __restrict__ hp, const float* __restrict__ bias,
                                 float* __restrict__ out, int N)
{
    int gt = blockIdx.x * blockDim.x + threadIdx.x;
    int w = gt >> 5, lane = gt & 31;
    if (w >= N) return;
    int beg = __ldg(off + w), end = __ldg(off + w + 1);
    int h = lane >> 2;
    float sd = __ldg(s_dst + w * 8 + h);

    float4 acc0 = make_float4(0.f, 0.f, 0.f, 0.f);
    float4 acc1 = make_float4(0.f, 0.f, 0.f, 0.f);
    float den = 0.f;

    int e = beg;
    for (; e + 2 <= end; e += 2) {
        int s0 = __ldg(csr + e), s1 = __ldg(csr + e + 1);
        float l0 = __ldg(s_src + s0 * 8 + h), l1 = __ldg(s_src + s1 * 8 + h);
        const float4* hv0 = (const float4*)(hp + (size_t)s0 * 256) + lane * 2;
        const float4* hv1 = (const float4*)(hp + (size_t)s1 * 256) + lane * 2;
        float4 v00 = __ldg(hv0), v01 = __ldg(hv0 + 1);
        float4 v10 = __ldg(hv1), v11 = __ldg(hv1 + 1);
        float e0 = l0 + sd; e0 = (e0 > 0.f) ? e0 : 0.2f * e0;
        float e1 = l1 + sd; e1 = (e1 > 0.f) ? e1 : 0.2f * e1;
        float x0 = __expf(e0), x1 = __expf(e1);
        den += x0 + x1;
        acc0.x += x0 * v00.x + x1 * v10.x; acc0.y += x0 * v00.y + x1 * v10.y;
        acc0.z += x0 * v00.z + x1 * v10.z; acc0.w += x0 * v00.w + x1 * v10.w;
        acc1.x += x0 * v01.x + x1 * v11.x; acc1.y += x0 * v01.y + x1 * v11.y;
        acc1.z += x0 * v01.z + x1 * v11.z; acc1.w += x0 * v01.w + x1 * v11.w;
    }
    if (e < end) {
        int s = __ldg(csr + e);
        float ee = __ldg(s_src + s * 8 + h) + sd;
        ee = (ee > 0.f) ? ee : 0.2f * ee;
        float ex = __expf(ee);
        den += ex;
        const float4* hv = (const float4*)(hp + (size_t)s * 256) + lane * 2;
        float4 v0 = __ldg(hv), v1 = __ldg(hv + 1);
        acc0.x += ex * v0.x; acc0.y += ex * v0.y; acc0.z += ex * v0.z; acc0.w += ex * v0.w;
        acc1.x += ex * v1.x; acc1.y += ex * v1.y; acc1.z += ex * v1.z; acc1.w += ex * v1.w;
    }
    float inv = 1.f / den;
    const float4* bb = (const float4*)(bias + lane * 8);
    float4 b0 = bb[0], b1 = bb[1];
    float o[8] = { acc0.x * inv + b0.x, acc0.y * inv + b0.y, acc0.z * inv + b0.z, acc0.w * inv + b0.w,
                   acc1.x * inv + b1.x, acc1.y * inv + b1.y, acc1.z * inv + b1.z, acc1.w * inv + b1.w };
#pragma unroll
    for (int i = 0; i < 8; ++i) o[i] = (o[i] > 0.f) ? o[i] : expm1f(o[i]);  // elu
    float4* ov = (float4*)(out + (size_t)w * 256 + lane * 8);
    ov[0] = make_float4(o[0], o[1], o[2], o[3]);
    ov[1] = make_float4(o[4], o[5], o[6], o[7]);
}

// ---------------- semantic score ----------------
__global__ void score_kernel(const float* __restrict__ t128, const float* __restrict__ W2,
                             float* __restrict__ scores, int N, int p)
{
    int gt = blockIdx.x * blockDim.x + threadIdx.x;
    int n = gt >> 5, lane = gt & 31;
    if (n >= N) return;
    const float* r = t128 + (size_t)n * 128;
    float v = r[lane] * W2[lane] + r[lane + 32] * W2[lane + 32]
            + r[lane + 64] * W2[lane + 64] + r[lane + 96] * W2[lane + 96];
#pragma unroll
    for (int o = 16; o > 0; o >>= 1) v += __shfl_xor_sync(0xffffffffu, v, o);
    if (lane == 0) scores[n * 3 + p] = v;
}

// ---------------- softmax over 3 metapaths + weighted sum ----------------
__global__ void combine_kernel(const float* __restrict__ e0, const float* __restrict__ e1,
                               const float* __restrict__ e2, const float* __restrict__ scores,
                               float* __restrict__ z, int N)
{
    int t = blockIdx.x * blockDim.x + threadIdx.x;
    if (t >= N * 64) return;
    int n = t >> 6, q = t & 63;
    float s0 = scores[n * 3], s1 = scores[n * 3 + 1], s2 = scores[n * 3 + 2];
    float m = fmaxf(s0, fmaxf(s1, s2));
    float w0 = __expf(s0 - m), w1 = __expf(s1 - m), w2 = __expf(s2 - m);
    float inv = 1.f / (w0 + w1 + w2);
    w0 *= inv; w1 *= inv; w2 *= inv;
    size_t offi = (size_t)n * 256 + q * 4;
    float4 a = *(const float4*)(e0 + offi);
    float4 b = *(const float4*)(e1 + offi);
    float4 c = *(const float4*)(e2 + offi);
    float4 o;
    o.x = w0 * a.x + w1 * b.x + w2 * c.x;
    o.y = w0 * a.y + w1 * b.y + w2 * c.y;
    o.z = w0 * a.z + w1 * b.z + w2 * c.z;
    o.w = w0 * a.w + w1 * b.w + w2 * c.w;
    *(float4*)(z + offi) = o;
}

// ---------------- classifier head ----------------
__global__ void logits_kernel(const float* __restrict__ hcls, const float* __restrict__ W2,
                              const float* __restrict__ b2, float* __restrict__ out, int N)
{
    int gt = blockIdx.x * blockDim.x + threadIdx.x;
    int n = gt >> 5, lane = gt & 31;
    if (n >= N) return;
    const float* r = hcls + (size_t)n * 128;
    float x0 = r[lane], x1 = r[lane + 32], x2 = r[lane + 64], x3 = r[lane + 96];
    float s0 = x0 * W2[lane * 2]            + x1 * W2[(lane + 32) * 2]
             + x2 * W2[(lane + 64) * 2]     + x3 * W2[(lane + 96) * 2];
    float s1 = x0 * W2[lane * 2 + 1]        + x1 * W2[(lane + 32) * 2 + 1]
             + x2 * W2[(lane + 64) * 2 + 1] + x3 * W2[(lane + 96) * 2 + 1];
#pragma unroll
    for (int o = 16; o > 0; o >>= 1) {
        s0 += __shfl_xor_sync(0xffffffffu, s0, o);
        s1 += __shfl_xor_sync(0xffffffffu, s1, o);
    }
    if (lane == 0) {
        out[n * 2]     = s0 + b2[0];
        out[n * 2 + 1] = s1 + b2[1];
    }
}

// ---------------- launch ----------------
extern "C" void kernel_launch(void* const* d_in, const int* in_sizes, int n_in,
                              void* d_out, int out_size)
{
    const float* x        = (const float*)d_in[0];
    const int*   edges    = (const int*)d_in[1];
    const float* proj_W   = (const float*)d_in[2];
    const float* proj_b   = (const float*)d_in[3];
    const float* gat_W    = (const float*)d_in[4];
    const float* gat_asrc = (const float*)d_in[5];
    const float* gat_adst = (const float*)d_in[6];
    const float* gat_b    = (const float*)d_in[7];
    const float* sem_W1   = (const float*)d_in[8];
    const float* sem_b1   = (const float*)d_in[9];
    const float* sem_W2   = (const float*)d_in[10];
    const float* cls_W1   = (const float*)d_in[11];
    const float* cls_b1   = (const float*)d_in[12];
    const float* cls_W2   = (const float*)d_in[13];
    const float* cls_b2   = (const float*)d_in[14];
    float* out = (float*)d_out;

    const int N = in_sizes[0] / 128;  // 50000
    const int E = in_sizes[1] / 6;    // 800000

    float *h0, *h, *hp, *ssrc, *sdst, *emb, *tbuf, *scores, *z, *hcls;
    int *deg, *off, *cursor, *csr, *partials;
    cudaGetSymbolAddress((void**)&h0,       g_h0);
    cudaGetSymbolAddress((void**)&h,        g_h);
    cudaGetSymbolAddress((void**)&hp,       g_hp);
    cudaGetSymbolAddress((void**)&ssrc,     g_ssrc);
    cudaGetSymbolAddress((void**)&sdst,     g_sdst);
    cudaGetSymbolAddress((void**)&emb,      g_emb);
    cudaGetSymbolAddress((void**)&tbuf,     g_t);
    cudaGetSymbolAddress((void**)&scores,   g_scores);
    cudaGetSymbolAddress((void**)&z,        g_z);
    cudaGetSymbolAddress((void**)&hcls,     g_hcls);
    cudaGetSymbolAddress((void**)&deg,      g_deg);
    cudaGetSymbolAddress((void**)&off,      g_off);
    cudaGetSymbolAddress((void**)&cursor,   g_cursor);
    cudaGetSymbolAddress((void**)&csr,      g_csr);
    cudaGetSymbolAddress((void**)&partials, g_partials);

    const int nb1024 = (N + 1023) / 1024;  // 49 for N=50000

    // h0 = x @ proj_W + proj_b
    {
        dim3 grid(256 / 64, (N + 127) / 128);
        gemm_kernel<<<grid, 256>>>(x, proj_W, proj_b, h0, N, 256, 128, 0);
    }

    for (int p = 0; p < 3; ++p) {
        const int* esrc = edges + (size_t)p * 2 * E;
        const int* edst = esrc + E;
        // Build dst-CSR (with self-loops) — reused by both layers
        deg_init_kernel<<<(N + 255) / 256, 256>>>(deg, N);
        deg_count_kernel<<<(E + 255) / 256, 256>>>(edst, deg, E);
        scan_local_kernel<<<nb1024, 1024>>>(deg, off, partials, N);
        scan_partials_kernel<<<1, 64>>>(partials, nb1024, off, N);
        scan_add_kernel<<<nb1024 * 4, 256>>>(off, partials, N);
        csr_init_kernel<<<(N + 255) / 256, 256>>>(off, cursor, csr, N);
        csr_fill_kernel<<<(E + 255) / 256, 256>>>(esrc, edst, cursor, csr, E);

        const float* hcur = h0;
        for (int l = 0; l < 2; ++l) {
            const float* W   = gat_W    + (size_t)(p * 2 + l) * 256 * 256;
            const float* as_ = gat_asrc + (size_t)(p * 2 + l) * 256;
            const float* ad_ = gat_adst + (size_t)(p * 2 + l) * 256;
            const float* bb  = gat_b    + (size_t)(p * 2 + l) * 256;

            dim3 grid(256 / 64, (N + 127) / 128);
            gemm_kernel<<<grid, 256>>>(hcur, W, nullptr, hp, N, 256, 256, 0);
            prep_kernel<<<(N * 8 + 255) / 256, 256>>>(hp, as_, ad_, ssrc, sdst, N);
            float* dst = (l == 0) ? h : (emb + (size_t)p * N * 256);
            aggregate_kernel<<<(N * 32 + 255) / 256, 256>>>(off, csr, ssrc, sdst, hp, bb, dst, N);
            hcur = h;
        }
    }

    // semantic attention
    for (int p = 0; p < 3; ++p) {
        dim3 grid(128 / 64, (N + 127) / 128);
        gemm_kernel<<<grid, 256>>>(emb + (size_t)p * N * 256, sem_W1, sem_b1, tbuf, N, 128, 256, 1);
        score_kernel<<<(N * 32 + 255) / 256, 256>>>(tbuf, sem_W2, scores, N, p);
    }
    combine_kernel<<<(N * 64 + 255) / 256, 256>>>(
        emb, emb + (size_t)N * 256, emb + (size_t)2 * N * 256, scores, z, N);

    // classifier
    {
        dim3 grid(128 / 64, (N + 127) / 128);
        gemm_kernel<<<grid, 256>>>(z, cls_W1, cls_b1, hcls, N, 128, 256, 2);
    }
    logits_kernel<<<(N * 32 + 255) / 256, 256>>>(hcls, cls_W2, cls_b2, out, N);
}

// round 10
// speedup vs baseline: 2.2240x; 1.1101x over previous
#include <cuda_runtime.h>
#include <cuda_bf16.h>
#include <math.h>

#define NN 50000
#define EE 800000

// ---------------- scratch ----------------
__device__ __align__(16) unsigned g_xH[NN * 64],  g_xL[NN * 64];      // x split pairs (K=128)
__device__ __align__(16) unsigned g_h0H[NN * 128], g_h0L[NN * 128];   // h0 split pairs (K=256)
__device__ __align__(16) float    g_hp[3ll * NN * 256];
__device__ __align__(16) unsigned g_hH[3ll * NN * 128], g_hL[3ll * NN * 128];
__device__ __align__(16) float    g_emb[3ll * NN * 256];
__device__ __align__(16) unsigned g_embH[3ll * NN * 128], g_embL[3ll * NN * 128];
__device__ __align__(16) unsigned g_zH[NN * 128], g_zL[NN * 128];
__device__ __align__(16) float    g_ssrc[3ll * NN * 8], g_sdst[3ll * NN * 8];
__device__ __align__(16) float    g_t[3ll * NN * 128];
__device__ __align__(16) float    g_scores[NN * 3];
__device__ __align__(16) float    g_hcls[NN * 128];
// weight splits: proj @0 (64*256), gat[p][l] @16384+(p*2+l)*32768, sem @212992, cls @229376
__device__ __align__(16) unsigned g_wH[245760], g_wL[245760];
// CSR (per metapath)
__device__ int g_deg[3ll * NN];
__device__ int g_off[3ll * (NN + 1)];
__device__ int g_cursor[3ll * NN];
__device__ int g_csr[3ll * (EE + NN)];
__device__ int g_partials[3 * 64];

// ---------------- bf16 split helper ----------------
__device__ __forceinline__ void split2(float a, float b, unsigned& hi, unsigned& lo)
{
    __nv_bfloat16 ah = __float2bfloat16_rn(a);
    __nv_bfloat16 bh = __float2bfloat16_rn(b);
    __nv_bfloat16 al = __float2bfloat16_rn(a - __bfloat162float(ah));
    __nv_bfloat16 bl = __float2bfloat16_rn(b - __bfloat162float(bh));
    __nv_bfloat162 h2 = __halves2bfloat162(ah, bh);
    __nv_bfloat162 l2 = __halves2bfloat162(al, bl);
    hi = *reinterpret_cast<unsigned*>(&h2);
    lo = *reinterpret_cast<unsigned*>(&l2);
}

__device__ __forceinline__ void mma_bf16(float (&d)[4], const unsigned (&a)[4], const unsigned (&b)[2])
{
    asm volatile("mma.sync.aligned.m16n8k16.row.col.f32.bf16.bf16.f32 "
        "{%0,%1,%2,%3}, {%4,%5,%6,%7}, {%8,%9}, {%0,%1,%2,%3};"
        : "+f"(d[0]), "+f"(d[1]), "+f"(d[2]), "+f"(d[3])
        : "r"(a[0]), "r"(a[1]), "r"(a[2]), "r"(a[3]), "r"(b[0]), "r"(b[1]));
}

// ---------------- split kernels ----------------
// contiguous fp32 -> packed bf16x2 hi/lo pairs (pair t = elems 2t,2t+1; rows have even width)
__global__ void split_pairs_kernel(const float* __restrict__ in, unsigned* __restrict__ oh,
                                   unsigned* __restrict__ ol, int npairs)
{
    int t = blockIdx.x * blockDim.x + threadIdx.x;
    if (t >= npairs) return;
    unsigned h, l;
    split2(in[2 * t], in[2 * t + 1], h, l);
    oh[t] = h; ol[t] = l;
}

// weight [K][N] fp32 -> [K/2][N] packed pairs along K
__global__ void split_w_kernel(const float* __restrict__ W, unsigned* __restrict__ oh,
                               unsigned* __restrict__ ol, int K2, int N)
{
    int t = blockIdx.x * blockDim.x + threadIdx.x;
    if (t >= K2 * N) return;
    int kp = t / N, n = t - kp * N;
    unsigned h, l;
    split2(W[(size_t)(2 * kp) * N + n], W[(size_t)(2 * kp + 1) * N + n], h, l);
    oh[t] = h; ol[t] = l;
}

// ---------------- pure-bf16x3 tensor-core GEMM ----------------
// A: [M][K2] packed pairs (row-major). B: [K2][N] packed pairs. C = act(A@B + bias).
// Optional fp32 output and/or packed split-pair output ([M][N/2]).
// BM=128, BN=64, BK=8 pairs (16 k). 256 threads = 8 warps (4m x 2n), warp tile 32x32.
__global__ void gemm_bf16_kernel(const unsigned* __restrict__ AH, const unsigned* __restrict__ AL,
                                 const unsigned* __restrict__ BH, const unsigned* __restrict__ BL,
                                 const float* __restrict__ bias,
                                 float* __restrict__ outF,
                                 unsigned* __restrict__ outH, unsigned* __restrict__ outL,
                                 int M, int N, int K2, int act)
{
    __shared__ unsigned AsH[128][12], AsL[128][12];
    __shared__ unsigned BsH[64][12],  BsL[64][12];

    const int tid = threadIdx.x;
    const int lane = tid & 31;
    const int warp = tid >> 5;
    const int wm = warp & 3, wn = warp >> 2;
    const int rowBase = blockIdx.y * 128;
    const int colBase = blockIdx.x * 64;
    const int g = lane >> 2, t = lane & 3;

    float acc[2][4][4];
#pragma unroll
    for (int mt = 0; mt < 2; ++mt)
#pragma unroll
        for (int nt = 0; nt < 4; ++nt)
#pragma unroll
            for (int i = 0; i < 4; ++i) acc[mt][nt][i] = 0.f;

    const int am = tid >> 1;          // 0..127
    const int aq = (tid & 1) * 4;     // 0 or 4 (pair offset, uint4)
    const int bn = tid & 63;          // 0..63
    const int bkp = tid >> 6;         // 0..3

    for (int kp0 = 0; kp0 < K2; kp0 += 8) {
        {
            int gr = rowBase + am;
            uint4 h4 = make_uint4(0, 0, 0, 0), l4 = make_uint4(0, 0, 0, 0);
            if (gr < M) {
                h4 = *(const uint4*)(AH + (size_t)gr * K2 + kp0 + aq);
                l4 = *(const uint4*)(AL + (size_t)gr * K2 + kp0 + aq);
            }
            *(uint4*)&AsH[am][aq] = h4;
            *(uint4*)&AsL[am][aq] = l4;
        }
        {
            size_t o0 = (size_t)(kp0 + bkp) * N + colBase + bn;
            size_t o1 = (size_t)(kp0 + bkp + 4) * N + colBase + bn;
            BsH[bn][bkp] = BH[o0];     BsL[bn][bkp] = BL[o0];
            BsH[bn][bkp + 4] = BH[o1]; BsL[bn][bkp + 4] = BL[o1];
        }
        __syncthreads();

        unsigned aH[2][4], aL[2][4], bH[4][2], bL[4][2];
#pragma unroll
        for (int mt = 0; mt < 2; ++mt) {
            int mr = wm * 32 + mt * 16;
            aH[mt][0] = AsH[mr + g][t];     aH[mt][1] = AsH[mr + 8 + g][t];
            aH[mt][2] = AsH[mr + g][t + 4]; aH[mt][3] = AsH[mr + 8 + g][t + 4];
            aL[mt][0] = AsL[mr + g][t];     aL[mt][1] = AsL[mr + 8 + g][t];
            aL[mt][2] = AsL[mr + g][t + 4]; aL[mt][3] = AsL[mr + 8 + g][t + 4];
        }
#pragma unroll
        for (int nt = 0; nt < 4; ++nt) {
            int nr = wn * 32 + nt * 8;
            bH[nt][0] = BsH[nr + g][t]; bH[nt][1] = BsH[nr + g][t + 4];
            bL[nt][0] = BsL[nr + g][t]; bL[nt][1] = BsL[nr + g][t + 4];
        }
#pragma unroll
        for (int mt = 0; mt < 2; ++mt)
#pragma unroll
            for (int nt = 0; nt < 4; ++nt) {
                mma_bf16(acc[mt][nt], aH[mt], bH[nt]);
                mma_bf16(acc[mt][nt], aL[mt], bH[nt]);
                mma_bf16(acc[mt][nt], aH[mt], bL[nt]);
            }
        __syncthreads();
    }

#pragma unroll
    for (int mt = 0; mt < 2; ++mt) {
#pragma unroll
        for (int nt = 0; nt < 4; ++nt) {
            int c = colBase + wn * 32 + nt * 8 + 2 * t;
            float b0 = bias ? bias[c] : 0.f;
            float b1 = bias ? bias[c + 1] : 0.f;
#pragma unroll
            for (int half = 0; half < 2; ++half) {
                int r = rowBase + wm * 32 + mt * 16 + g + half * 8;
                if (r >= M) continue;
                float v0 = acc[mt][nt][half * 2 + 0] + b0;
                float v1 = acc[mt][nt][half * 2 + 1] + b1;
                if (act == 1) { v0 = tanhf(v0); v1 = tanhf(v1); }
                else if (act == 2) { v0 = fmaxf(v0, 0.f); v1 = fmaxf(v1, 0.f); }
                if (outF) *(float2*)(outF + (size_t)r * N + c) = make_float2(v0, v1);
                if (outH) {
                    unsigned h, l;
                    split2(v0, v1, h, l);
                    size_t oi = (size_t)r * (N >> 1) + (c >> 1);
                    outH[oi] = h; outL[oi] = l;
                }
            }
        }
    }
}

// ---------------- CSR build ----------------
__global__ void deg_init_kernel(int* __restrict__ deg, int N)
{
    int t = blockIdx.x * blockDim.x + threadIdx.x;
    if (t < N) deg[t] = 1;  // self-loop
}

__global__ void deg_count_kernel(const int* __restrict__ edst, int* __restrict__ deg, int E)
{
    int t = blockIdx.x * blockDim.x + threadIdx.x;
    if (t < E) atomicAdd(deg + __ldg(edst + t), 1);
}

__global__ void scan_local_kernel(const int* __restrict__ deg, int* __restrict__ off,
                                  int* __restrict__ partials, int N)
{
    __shared__ int sm[1024];
    int b = blockIdx.x, tid = threadIdx.x;
    int i = b * 1024 + tid;
    int v = (i < N) ? deg[i] : 0;
    sm[tid] = v;
    __syncthreads();
    for (int o = 1; o < 1024; o <<= 1) {
        int x = (tid >= o) ? sm[tid - o] : 0;
        __syncthreads();
        sm[tid] += x;
        __syncthreads();
    }
    if (i < N) off[i] = sm[tid] - v;
    if (tid == 1023) partials[b] = sm[1023];
}

__global__ void scan_partials_kernel(int* __restrict__ partials, int nb,
                                     int* __restrict__ off, int N)
{
    __shared__ int sm[64];
    int tid = threadIdx.x;
    int v = (tid < nb) ? partials[tid] : 0;
    sm[tid] = v;
    __syncthreads();
    for (int o = 1; o < 64; o <<= 1) {
        int x = (tid >= o) ? sm[tid - o] : 0;
        __syncthreads();
        sm[tid] += x;
        __syncthreads();
    }
    if (tid < nb) partials[tid] = sm[tid] - v;
    if (tid == 63) off[N] = sm[63];
}

__global__ void scan_add_kernel(int* __restrict__ off, const int* __restrict__ partials, int N)
{
    int i = blockIdx.x * blockDim.x + threadIdx.x;
    if (i < N) off[i] += partials[blockIdx.x >> 2];
}

__global__ void csr_init_kernel(const int* __restrict__ off, int* __restrict__ cursor,
                                int* __restrict__ csr, int N)
{
    int t = blockIdx.x * blockDim.x + threadIdx.x;
    if (t >= N) return;
    int o = off[t];
    csr[o] = t;
    cursor[t] = o + 1;
}

__global__ void csr_fill_kernel(const int* __restrict__ esrc, const int* __restrict__ edst,
                                int* __restrict__ cursor, int* __restrict__ csr, int E)
{
    int t = blockIdx.x * blockDim.x + threadIdx.x;
    if (t >= E) return;
    int d = __ldg(edst + t);
    int pos = atomicAdd(cursor + d, 1);
    csr[pos] = __ldg(esrc + t);
}

// ---------------- attention logit halves ----------------
__global__ void prep_kernel(const float* __restrict__ hp,
                            const float* __restrict__ a_src, const float* __restrict__ a_dst,
                            float* __restrict__ s_src, float* __restrict__ s_dst, int N)
{
    int t = blockIdx.x * blockDim.x + threadIdx.x;
    if (t >= N * 8) return;
    int n = t >> 3, h = t & 7;
    const float4* hv = (const float4*)(hp + (size_t)n * 256 + h * 32);
    const float4* av = (const float4*)(a_src + h * 32);
    const float4* bv = (const float4*)(a_dst + h * 32);
    float ss = 0.f, sd = 0.f;
#pragma unroll
    for (int i = 0; i < 8; ++i) {
        float4 x = hv[i], a = av[i], b = bv[i];
        ss += x.x * a.x + x.y * a.y + x.z * a.z + x.w * a.w;
        sd += x.x * b.x + x.y * b.y + x.z * b.z + x.w * b.w;
    }
    s_src[t] = ss;
    s_dst[t] = sd;
}

// ---------------- warp-per-node gather aggregation (fused softmax/bias/elu, split output) ----------------
__global__ void aggregate_kernel(const int* __restrict__ off, const int* __restrict__ csr,
                                 const float* __restrict__ s_src, const float* __restrict__ s_dst,
                                 const float* __restrict__ hp, const float* __restrict__ bias,
                                 float* __restrict__ outF,
                                 unsigned* __restrict__ outH, unsigned* __restrict__ outL, int N)
{
    int gt = blockIdx.x * blockDim.x + threadIdx.x;
    int w = gt >> 5, lane = gt & 31;
    if (w >= N) return;
    int beg = __ldg(off + w), end = __ldg(off + w + 1);
    int h = lane >> 2;
    float sd = __ldg(s_dst + w * 8 + h);

    float4 acc0 = make_float4(0.f, 0.f, 0.f, 0.f);
    float4 acc1 = make_float4(0.f, 0.f, 0.f, 0.f);
    float den = 0.f;

    int e = beg;
    for (; e + 2 <= end; e += 2) {
        int s0 = __ldg(csr + e), s1 = __ldg(csr + e + 1);
        float l0 = __ldg(s_src + s0 * 8 + h), l1 = __ldg(s_src + s1 * 8 + h);
        const float4* hv0 = (const float4*)(hp + (size_t)s0 * 256) + lane * 2;
        const float4* hv1 = (const float4*)(hp + (size_t)s1 * 256) + lane * 2;
        float4 v00 = __ldg(hv0), v01 = __ldg(hv0 + 1);
        float4 v10 = __ldg(hv1), v11 = __ldg(hv1 + 1);
        float e0 = l0 + sd; e0 = (e0 > 0.f) ? e0 : 0.2f * e0;
        float e1 = l1 + sd; e1 = (e1 > 0.f) ? e1 : 0.2f * e1;
        float x0 = __expf(e0), x1 = __expf(e1);
        den += x0 + x1;
        acc0.x += x0 * v00.x + x1 * v10.x; acc0.y += x0 * v00.y + x1 * v10.y;
        acc0.z += x0 * v00.z + x1 * v10.z; acc0.w += x0 * v00.w + x1 * v10.w;
        acc1.x += x0 * v01.x + x1 * v11.x; acc1.y += x0 * v01.y + x1 * v11.y;
        acc1.z += x0 * v01.z + x1 * v11.z; acc1.w += x0 * v01.w + x1 * v11.w;
    }
    if (e < end) {
        int s = __ldg(csr + e);
        float ee = __ldg(s_src + s * 8 + h) + sd;
        ee = (ee > 0.f) ? ee : 0.2f * ee;
        float ex = __expf(ee);
        den += ex;
        const float4* hv = (const float4*)(hp + (size_t)s * 256) + lane * 2;
        float4 v0 = __ldg(hv), v1 = __ldg(hv + 1);
        acc0.x += ex * v0.x; acc0.y += ex * v0.y; acc0.z += ex * v0.z; acc0.w += ex * v0.w;
        acc1.x += ex * v1.x; acc1.y += ex * v1.y; acc1.z += ex * v1.z; acc1.w += ex * v1.w;
    }
    float inv = 1.f / den;
    const float4* bb = (const float4*)(bias + lane * 8);
    float4 b0 = bb[0], b1 = bb[1];
    float o[8] = { acc0.x * inv + b0.x, acc0.y * inv + b0.y, acc0.z * inv + b0.z, acc0.w * inv + b0.w,
                   acc1.x * inv + b1.x, acc1.y * inv + b1.y, acc1.z * inv + b1.z, acc1.w * inv + b1.w };
#pragma unroll
    for (int i = 0; i < 8; ++i) o[i] = (o[i] > 0.f) ? o[i] : expm1f(o[i]);  // elu
    if (outF) {
        float4* ov = (float4*)(outF + (size_t)w * 256 + lane * 8);
        ov[0] = make_float4(o[0], o[1], o[2], o[3]);
        ov[1] = make_float4(o[4], o[5], o[6], o[7]);
    }
#pragma unroll
    for (int j = 0; j < 4; ++j) {
        unsigned hh, ll;
        split2(o[2 * j], o[2 * j + 1], hh, ll);
        size_t oi = (size_t)w * 128 + lane * 4 + j;
        outH[oi] = hh; outL[oi] = ll;
    }
}

// ---------------- semantic score ----------------
__global__ void score_kernel(const float* __restrict__ t128, const float* __restrict__ W2,
                             float* __restrict__ scores, int N, int p)
{
    int gt = blockIdx.x * blockDim.x + threadIdx.x;
    int n = gt >> 5, lane = gt & 31;
    if (n >= N) return;
    const float* r = t128 + (size_t)n * 128;
    float v = r[lane] * W2[lane] + r[lane + 32] * W2[lane + 32]
            + r[lane + 64] * W2[lane + 64] + r[lane + 96] * W2[lane + 96];
#pragma unroll
    for (int o = 16; o > 0; o >>= 1) v += __shfl_xor_sync(0xffffffffu, v, o);
    if (lane == 0) scores[n * 3 + p] = v;
}

// ---------------- softmax over 3 metapaths + weighted sum (split output) ----------------
__global__ void combine_kernel(const float* __restrict__ e0, const float* __restrict__ e1,
                               const float* __restrict__ e2, const float* __restrict__ scores,
                               unsigned* __restrict__ zH, unsigned* __restrict__ zL, int N)
{
    int t = blockIdx.x * blockDim.x + threadIdx.x;
    if (t >= N * 64) return;
    int n = t >> 6, q = t & 63;
    float s0 = scores[n * 3], s1 = scores[n * 3 + 1], s2 = scores[n * 3 + 2];
    float m = fmaxf(s0, fmaxf(s1, s2));
    float w0 = __expf(s0 - m), w1 = __expf(s1 - m), w2 = __expf(s2 - m);
    float inv = 1.f / (w0 + w1 + w2);
    w0 *= inv; w1 *= inv; w2 *= inv;
    size_t offi = (size_t)n * 256 + q * 4;
    float4 a = *(const float4*)(e0 + offi);
    float4 b = *(const float4*)(e1 + offi);
    float4 c = *(const float4*)(e2 + offi);
    float ox = w0 * a.x + w1 * b.x + w2 * c.x;
    float oy = w0 * a.y + w1 * b.y + w2 * c.y;
    float oz = w0 * a.z + w1 * b.z + w2 * c.z;
    float ow = w0 * a.w + w1 * b.w + w2 * c.w;
    unsigned h, l;
    size_t zi = (size_t)n * 128 + q * 2;
    split2(ox, oy, h, l); zH[zi] = h;     zL[zi] = l;
    split2(oz, ow, h, l); zH[zi + 1] = h; zL[zi + 1] = l;
}

// ---------------- classifier head ----------------
__global__ void logits_kernel(const float* __restrict__ hcls, const float* __restrict__ W2,
                              const float* __restrict__ b2, float* __restrict__ out, int N)
{
    int gt = blockIdx.x * blockDim.x + threadIdx.x;
    int n = gt >> 5, lane = gt & 31;
    if (n >= N) return;
    const float* r = hcls + (size_t)n * 128;
    float x0 = r[lane], x1 = r[lane + 32], x2 = r[lane + 64], x3 = r[lane + 96];
    float s0 = x0 * W2[lane * 2]            + x1 * W2[(lane + 32) * 2]
             + x2 * W2[(lane + 64) * 2]     + x3 * W2[(lane + 96) * 2];
    float s1 = x0 * W2[lane * 2 + 1]        + x1 * W2[(lane + 32) * 2 + 1]
             + x2 * W2[(lane + 64) * 2 + 1] + x3 * W2[(lane + 96) * 2 + 1];
#pragma unroll
    for (int o = 16; o > 0; o >>= 1) {
        s0 += __shfl_xor_sync(0xffffffffu, s0, o);
        s1 += __shfl_xor_sync(0xffffffffu, s1, o);
    }
    if (lane == 0) {
        out[n * 2]     = s0 + b2[0];
        out[n * 2 + 1] = s1 + b2[1];
    }
}

// ---------------- launch ----------------
extern "C" void kernel_launch(void* const* d_in, const int* in_sizes, int n_in,
                              void* d_out, int out_size)
{
    const float* x        = (const float*)d_in[0];
    const int*   edges    = (const int*)d_in[1];
    const float* proj_W   = (const float*)d_in[2];
    const float* proj_b   = (const float*)d_in[3];
    const float* gat_W    = (const float*)d_in[4];
    const float* gat_asrc = (const float*)d_in[5];
    const float* gat_adst = (const float*)d_in[6];
    const float* gat_b    = (const float*)d_in[7];
    const float* sem_W1   = (const float*)d_in[8];
    const float* sem_b1   = (const float*)d_in[9];
    const float* sem_W2   = (const float*)d_in[10];
    const float* cls_W1   = (const float*)d_in[11];
    const float* cls_b1   = (const float*)d_in[12];
    const float* cls_W2   = (const float*)d_in[13];
    const float* cls_b2   = (const float*)d_in[14];
    float* out = (float*)d_out;

    const int N = in_sizes[0] / 128;  // 50000
    const int E = in_sizes[1] / 6;    // 800000

    unsigned *xH, *xL, *h0H, *h0L, *hH, *hL, *embH, *embL, *zH, *zL, *wH, *wL;
    float *hp, *emb, *ssrc, *sdst, *tbuf, *scores, *hcls;
    int *deg, *off, *cursor, *csr, *partials;
    cudaGetSymbolAddress((void**)&xH,   g_xH);   cudaGetSymbolAddress((void**)&xL,   g_xL);
    cudaGetSymbolAddress((void**)&h0H,  g_h0H);  cudaGetSymbolAddress((void**)&h0L,  g_h0L);
    cudaGetSymbolAddress((void**)&hH,   g_hH);   cudaGetSymbolAddress((void**)&hL,   g_hL);
    cudaGetSymbolAddress((void**)&embH, g_embH); cudaGetSymbolAddress((void**)&embL, g_embL);
    cudaGetSymbolAddress((void**)&zH,   g_zH);   cudaGetSymbolAddress((void**)&zL,   g_zL);
    cudaGetSymbolAddress((void**)&wH,   g_wH);   cudaGetSymbolAddress((void**)&wL,   g_wL);
    cudaGetSymbolAddress((void**)&hp,   g_hp);
    cudaGetSymbolAddress((void**)&emb,  g_emb);
    cudaGetSymbolAddress((void**)&ssrc, g_ssrc); cudaGetSymbolAddress((void**)&sdst, g_sdst);
    cudaGetSymbolAddress((void**)&tbuf, g_t);
    cudaGetSymbolAddress((void**)&scores, g_scores);
    cudaGetSymbolAddress((void**)&hcls, g_hcls);
    cudaGetSymbolAddress((void**)&deg,  g_deg);  cudaGetSymbolAddress((void**)&off, g_off);
    cudaGetSymbolAddress((void**)&cursor, g_cursor);
    cudaGetSymbolAddress((void**)&csr,  g_csr);  cudaGetSymbolAddress((void**)&partials, g_partials);

    static bool s_init = false;
    static cudaStream_t st1, st2;
    static cudaEvent_t evRoot, evJ1, evJ2;
    if (!s_init) {
        cudaStreamCreateWithFlags(&st1, cudaStreamNonBlocking);
        cudaStreamCreateWithFlags(&st2, cudaStreamNonBlocking);
        cudaEventCreateWithFlags(&evRoot, cudaEventDisableTiming);
        cudaEventCreateWithFlags(&evJ1, cudaEventDisableTiming);
        cudaEventCreateWithFlags(&evJ2, cudaEventDisableTiming);
        s_init = true;
    }
    cudaStream_t streams[3] = { (cudaStream_t)0, st1, st2 };

    const int nb1024 = (N + 1023) / 1024;
    const int OFF_PROJ = 0;
    const int OFF_GAT  = 16384;       // + (p*2+l)*32768
    const int OFF_SEM  = 212992;
    const int OFF_CLS  = 229376;

    // --- stream 0: weight splits, x split, proj GEMM ---
    split_pairs_kernel<<<(N * 64 + 255) / 256, 256>>>(x, xH, xL, N * 64);
    split_w_kernel<<<(64 * 256 + 255) / 256, 256>>>(proj_W, wH + OFF_PROJ, wL + OFF_PROJ, 64, 256);
    for (int i = 0; i < 6; ++i)
        split_w_kernel<<<(128 * 256 + 255) / 256, 256>>>(gat_W + (size_t)i * 65536,
            wH + OFF_GAT + i * 32768, wL + OFF_GAT + i * 32768, 128, 256);
    split_w_kernel<<<(128 * 128 + 255) / 256, 256>>>(sem_W1, wH + OFF_SEM, wL + OFF_SEM, 128, 128);
    split_w_kernel<<<(128 * 128 + 255) / 256, 256>>>(cls_W1, wH + OFF_CLS, wL + OFF_CLS, 128, 128);

    {   // h0 = x @ proj_W + proj_b  -> split pairs only
        dim3 grid(4, (N + 127) / 128);
        gemm_bf16_kernel<<<grid, 256>>>(xH, xL, wH + OFF_PROJ, wL + OFF_PROJ, proj_b,
                                        nullptr, h0H, h0L, N, 256, 64, 0);
    }
    cudaEventRecord(evRoot, 0);
    cudaStreamWaitEvent(st1, evRoot, 0);
    cudaStreamWaitEvent(st2, evRoot, 0);

    // --- per-metapath pipelines on 3 streams ---
    for (int p = 0; p < 3; ++p) {
        cudaStream_t S = streams[p];
        const int* esrc = edges + (size_t)p * 2 * E;
        const int* edst = esrc + E;
        int* deg_p = deg + (size_t)p * NN;
        int* off_p = off + (size_t)p * (NN + 1);
        int* cur_p = cursor + (size_t)p * NN;
        int* csr_p = csr + (size_t)p * (EE + NN);
        int* par_p = partials + p * 64;
        float* hp_p = hp + (size_t)p * NN * 256;
        float* ss_p = ssrc + (size_t)p * NN * 8;
        float* sd_p = sdst + (size_t)p * NN * 8;
        unsigned* hH_p = hH + (size_t)p * NN * 128;
        unsigned* hL_p = hL + (size_t)p * NN * 128;
        unsigned* eH_p = embH + (size_t)p * NN * 128;
        unsigned* eL_p = embL + (size_t)p * NN * 128;
        float* emb_p = emb + (size_t)p * NN * 256;
        float* t_p = tbuf + (size_t)p * NN * 128;

        deg_init_kernel<<<(N + 255) / 256, 256, 0, S>>>(deg_p, N);
        deg_count_kernel<<<(E + 255) / 256, 256, 0, S>>>(edst, deg_p, E);
        scan_local_kernel<<<nb1024, 1024, 0, S>>>(deg_p, off_p, par_p, N);
        scan_partials_kernel<<<1, 64, 0, S>>>(par_p, nb1024, off_p, N);
        scan_add_kernel<<<nb1024 * 4, 256, 0, S>>>(off_p, par_p, N);
        csr_init_kernel<<<(N + 255) / 256, 256, 0, S>>>(off_p, cur_p, csr_p, N);
        csr_fill_kernel<<<(E + 255) / 256, 256, 0, S>>>(esrc, edst, cur_p, csr_p, E);

        for (int l = 0; l < 2; ++l) {
            const unsigned* AHc = (l == 0) ? h0H : hH_p;
            const unsigned* ALc = (l == 0) ? h0L : hL_p;
            const unsigned* WHc = wH + OFF_GAT + (p * 2 + l) * 32768;
            const unsigned* WLc = wL + OFF_GAT + (p * 2 + l) * 32768;
            const float* as_ = gat_asrc + (size_t)(p * 2 + l) * 256;
            const float* ad_ = gat_adst + (size_t)(p * 2 + l) * 256;
            const float* bb  = gat_b    + (size_t)(p * 2 + l) * 256;

            dim3 grid(4, (N + 127) / 128);
            gemm_bf16_kernel<<<grid, 256, 0, S>>>(AHc, ALc, WHc, WLc, nullptr,
                                                  hp_p, nullptr, nullptr, N, 256, 128, 0);
            prep_kernel<<<(N * 8 + 255) / 256, 256, 0, S>>>(hp_p, as_, ad_, ss_p, sd_p, N);
            if (l == 0)
                aggregate_kernel<<<(N * 32 + 255) / 256, 256, 0, S>>>(
                    off_p, csr_p, ss_p, sd_p, hp_p, bb, nullptr, hH_p, hL_p, N);
            else
                aggregate_kernel<<<(N * 32 + 255) / 256, 256, 0, S>>>(
                    off_p, csr_p, ss_p, sd_p, hp_p, bb, emb_p, eH_p, eL_p, N);
        }
        // semantic attention score for this metapath
        {
            dim3 grid(2, (N + 127) / 128);
            gemm_bf16_kernel<<<grid, 256, 0, S>>>(eH_p, eL_p, wH + OFF_SEM, wL + OFF_SEM, sem_b1,
                                                  t_p, nullptr, nullptr, N, 128, 128, 1);
        }
        score_kernel<<<(N * 32 + 255) / 256, 256, 0, S>>>(t_p, sem_W2, scores, N, p);
    }
    cudaEventRecord(evJ1, st1);
    cudaEventRecord(evJ2, st2);
    cudaStreamWaitEvent((cudaStream_t)0, evJ1, 0);
    cudaStreamWaitEvent((cudaStream_t)0, evJ2, 0);

    // --- join: combine + classifier on stream 0 ---
    combine_kernel<<<(N * 64 + 255) / 256, 256>>>(
        emb, emb + (size_t)NN * 256, emb + (size_t)2 * NN * 256, scores, zH, zL, N);
    {
        dim3 grid(2, (N + 127) / 128);
        gemm_bf16_kernel<<<grid, 256>>>(zH, zL, wH + OFF_CLS, wL + OFF_CLS, cls_b1,
                                        hcls, nullptr, nullptr, N, 128, 128, 2);
    }
    logits_kernel<<<(N * 32 + 255) / 256, 256>>>(hcls, cls_W2, cls_b2, out, N);
}

// round 11
// speedup vs baseline: 2.4185x; 1.0874x over previous
#include <cuda_runtime.h>
#include <cuda_bf16.h>
#include <cuda_fp16.h>
#include <math.h>

#define NN 50000
#define EE 800000

// ---------------- scratch ----------------
__device__ __align__(16) unsigned g_xH[NN * 64],  g_xL[NN * 64];      // x split pairs (K=128)
__device__ __align__(16) unsigned g_h0H[NN * 128], g_h0L[NN * 128];   // h0 split pairs (K=256)
__device__ __align__(16) unsigned g_hpP[3ll * NN * 128];              // hp packed fp16 (256 feats)
__device__ __align__(16) unsigned g_hH[3ll * NN * 128], g_hL[3ll * NN * 128];
__device__ __align__(16) float    g_emb[3ll * NN * 256];
__device__ __align__(16) unsigned g_embH[3ll * NN * 128], g_embL[3ll * NN * 128];
__device__ __align__(16) unsigned g_zH[NN * 128], g_zL[NN * 128];
__device__ __align__(16) float    g_ssrc[3ll * NN * 8], g_sdst[3ll * NN * 8];
__device__ __align__(16) float    g_t[3ll * NN * 128];
__device__ __align__(16) float    g_scores[NN * 3];
__device__ __align__(16) float    g_hcls[NN * 128];
// weight splits: proj @0 (64*256), gat[p][l] @16384+(p*2+l)*32768, sem @212992, cls @229376
__device__ __align__(16) unsigned g_wH[245760], g_wL[245760];
// CSR (per metapath)
__device__ int g_deg[3ll * NN];
__device__ int g_off[3ll * (NN + 1)];
__device__ int g_cursor[3ll * NN];
__device__ int g_csr[3ll * (EE + NN)];
__device__ int g_partials[3 * 64];

// ---------------- helpers ----------------
__device__ __forceinline__ void split2(float a, float b, unsigned& hi, unsigned& lo)
{
    __nv_bfloat16 ah = __float2bfloat16_rn(a);
    __nv_bfloat16 bh = __float2bfloat16_rn(b);
    __nv_bfloat16 al = __float2bfloat16_rn(a - __bfloat162float(ah));
    __nv_bfloat16 bl = __float2bfloat16_rn(b - __bfloat162float(bh));
    __nv_bfloat162 h2 = __halves2bfloat162(ah, bh);
    __nv_bfloat162 l2 = __halves2bfloat162(al, bl);
    hi = *reinterpret_cast<unsigned*>(&h2);
    lo = *reinterpret_cast<unsigned*>(&l2);
}

__device__ __forceinline__ unsigned packh2(float a, float b)
{
    __half2 h = __floats2half2_rn(a, b);
    return *reinterpret_cast<unsigned*>(&h);
}

__device__ __forceinline__ float2 unpackh2(unsigned u)
{
    __half2 h = *reinterpret_cast<__half2*>(&u);
    return __half22float2(h);
}

__device__ __forceinline__ void mma_bf16(float (&d)[4], const unsigned (&a)[4], const unsigned (&b)[2])
{
    asm volatile("mma.sync.aligned.m16n8k16.row.col.f32.bf16.bf16.f32 "
        "{%0,%1,%2,%3}, {%4,%5,%6,%7}, {%8,%9}, {%0,%1,%2,%3};"
        : "+f"(d[0]), "+f"(d[1]), "+f"(d[2]), "+f"(d[3])
        : "r"(a[0]), "r"(a[1]), "r"(a[2]), "r"(a[3]), "r"(b[0]), "r"(b[1]));
}

// ---------------- split kernels ----------------
__global__ void split_pairs_kernel(const float* __restrict__ in, unsigned* __restrict__ oh,
                                   unsigned* __restrict__ ol, int npairs)
{
    int t = blockIdx.x * blockDim.x + threadIdx.x;
    if (t >= npairs) return;
    unsigned h, l;
    split2(in[2 * t], in[2 * t + 1], h, l);
    oh[t] = h; ol[t] = l;
}

__global__ void split_w_kernel(const float* __restrict__ W, unsigned* __restrict__ oh,
                               unsigned* __restrict__ ol, int K2, int N)
{
    int t = blockIdx.x * blockDim.x + threadIdx.x;
    if (t >= K2 * N) return;
    int kp = t / N, n = t - kp * N;
    unsigned h, l;
    split2(W[(size_t)(2 * kp) * N + n], W[(size_t)(2 * kp + 1) * N + n], h, l);
    oh[t] = h; ol[t] = l;
}

// ---------------- pure-bf16x3 tensor-core GEMM ----------------
// A: [M][K2] packed bf16 pairs. B: [K2][N] packed pairs. C = act(A@B + bias).
// Outputs (any subset): fp32 (outF), bf16 split pairs (outH/outL), packed fp16 (outP).
__global__ void gemm_bf16_kernel(const unsigned* __restrict__ AH, const unsigned* __restrict__ AL,
                                 const unsigned* __restrict__ BH, const unsigned* __restrict__ BL,
                                 const float* __restrict__ bias,
                                 float* __restrict__ outF,
                                 unsigned* __restrict__ outH, unsigned* __restrict__ outL,
                                 unsigned* __restrict__ outP,
                                 int M, int N, int K2, int act)
{
    __shared__ unsigned AsH[128][12], AsL[128][12];
    __shared__ unsigned BsH[64][12],  BsL[64][12];

    const int tid = threadIdx.x;
    const int lane = tid & 31;
    const int warp = tid >> 5;
    const int wm = warp & 3, wn = warp >> 2;
    const int rowBase = blockIdx.y * 128;
    const int colBase = blockIdx.x * 64;
    const int g = lane >> 2, t = lane & 3;

    float acc[2][4][4];
#pragma unroll
    for (int mt = 0; mt < 2; ++mt)
#pragma unroll
        for (int nt = 0; nt < 4; ++nt)
#pragma unroll
            for (int i = 0; i < 4; ++i) acc[mt][nt][i] = 0.f;

    const int am = tid >> 1;
    const int aq = (tid & 1) * 4;
    const int bn = tid & 63;
    const int bkp = tid >> 6;

    for (int kp0 = 0; kp0 < K2; kp0 += 8) {
        {
            int gr = rowBase + am;
            uint4 h4 = make_uint4(0, 0, 0, 0), l4 = make_uint4(0, 0, 0, 0);
            if (gr < M) {
                h4 = *(const uint4*)(AH + (size_t)gr * K2 + kp0 + aq);
                l4 = *(const uint4*)(AL + (size_t)gr * K2 + kp0 + aq);
            }
            *(uint4*)&AsH[am][aq] = h4;
            *(uint4*)&AsL[am][aq] = l4;
        }
        {
            size_t o0 = (size_t)(kp0 + bkp) * N + colBase + bn;
            size_t o1 = (size_t)(kp0 + bkp + 4) * N + colBase + bn;
            BsH[bn][bkp] = BH[o0];     BsL[bn][bkp] = BL[o0];
            BsH[bn][bkp + 4] = BH[o1]; BsL[bn][bkp + 4] = BL[o1];
        }
        __syncthreads();

        unsigned aH[2][4], aL[2][4], bH[4][2], bL[4][2];
#pragma unroll
        for (int mt = 0; mt < 2; ++mt) {
            int mr = wm * 32 + mt * 16;
            aH[mt][0] = AsH[mr + g][t];     aH[mt][1] = AsH[mr + 8 + g][t];
            aH[mt][2] = AsH[mr + g][t + 4]; aH[mt][3] = AsH[mr + 8 + g][t + 4];
            aL[mt][0] = AsL[mr + g][t];     aL[mt][1] = AsL[mr + 8 + g][t];
            aL[mt][2] = AsL[mr + g][t + 4]; aL[mt][3] = AsL[mr + 8 + g][t + 4];
        }
#pragma unroll
        for (int nt = 0; nt < 4; ++nt) {
            int nr = wn * 32 + nt * 8;
            bH[nt][0] = BsH[nr + g][t]; bH[nt][1] = BsH[nr + g][t + 4];
            bL[nt][0] = BsL[nr + g][t]; bL[nt][1] = BsL[nr + g][t + 4];
        }
#pragma unroll
        for (int mt = 0; mt < 2; ++mt)
#pragma unroll
            for (int nt = 0; nt < 4; ++nt) {
                mma_bf16(acc[mt][nt], aH[mt], bH[nt]);
                mma_bf16(acc[mt][nt], aL[mt], bH[nt]);
                mma_bf16(acc[mt][nt], aH[mt], bL[nt]);
            }
        __syncthreads();
    }

#pragma unroll
    for (int mt = 0; mt < 2; ++mt) {
#pragma unroll
        for (int nt = 0; nt < 4; ++nt) {
            int c = colBase + wn * 32 + nt * 8 + 2 * t;
            float b0 = bias ? bias[c] : 0.f;
            float b1 = bias ? bias[c + 1] : 0.f;
#pragma unroll
            for (int half = 0; half < 2; ++half) {
                int r = rowBase + wm * 32 + mt * 16 + g + half * 8;
                if (r >= M) continue;
                float v0 = acc[mt][nt][half * 2 + 0] + b0;
                float v1 = acc[mt][nt][half * 2 + 1] + b1;
                if (act == 1) { v0 = tanhf(v0); v1 = tanhf(v1); }
                else if (act == 2) { v0 = fmaxf(v0, 0.f); v1 = fmaxf(v1, 0.f); }
                if (outF) *(float2*)(outF + (size_t)r * N + c) = make_float2(v0, v1);
                if (outP) outP[(size_t)r * (N >> 1) + (c >> 1)] = packh2(v0, v1);
                if (outH) {
                    unsigned h, l;
                    split2(v0, v1, h, l);
                    size_t oi = (size_t)r * (N >> 1) + (c >> 1);
                    outH[oi] = h; outL[oi] = l;
                }
            }
        }
    }
}

// ---------------- CSR build ----------------
__global__ void deg_init_kernel(int* __restrict__ deg, int N)
{
    int t = blockIdx.x * blockDim.x + threadIdx.x;
    if (t < N) deg[t] = 1;  // self-loop
}

__global__ void deg_count_kernel(const int* __restrict__ edst, int* __restrict__ deg, int E)
{
    int t = blockIdx.x * blockDim.x + threadIdx.x;
    if (t < E) atomicAdd(deg + __ldg(edst + t), 1);
}

__global__ void scan_local_kernel(const int* __restrict__ deg, int* __restrict__ off,
                                  int* __restrict__ partials, int N)
{
    __shared__ int sm[1024];
    int b = blockIdx.x, tid = threadIdx.x;
    int i = b * 1024 + tid;
    int v = (i < N) ? deg[i] : 0;
    sm[tid] = v;
    __syncthreads();
    for (int o = 1; o < 1024; o <<= 1) {
        int x = (tid >= o) ? sm[tid - o] : 0;
        __syncthreads();
        sm[tid] += x;
        __syncthreads();
    }
    if (i < N) off[i] = sm[tid] - v;
    if (tid == 1023) partials[b] = sm[1023];
}

__global__ void scan_partials_kernel(int* __restrict__ partials, int nb,
                                     int* __restrict__ off, int N)
{
    __shared__ int sm[64];
    int tid = threadIdx.x;
    int v = (tid < nb) ? partials[tid] : 0;
    sm[tid] = v;
    __syncthreads();
    for (int o = 1; o < 64; o <<= 1) {
        int x = (tid >= o) ? sm[tid - o] : 0;
        __syncthreads();
        sm[tid] += x;
        __syncthreads();
    }
    if (tid < nb) partials[tid] = sm[tid] - v;
    if (tid == 63) off[N] = sm[63];
}

__global__ void scan_add_kernel(int* __restrict__ off, const int* __restrict__ partials, int N)
{
    int i = blockIdx.x * blockDim.x + threadIdx.x;
    if (i < N) off[i] += partials[blockIdx.x >> 2];
}

__global__ void csr_init_kernel(const int* __restrict__ off, int* __restrict__ cursor,
                                int* __restrict__ csr, int N)
{
    int t = blockIdx.x * blockDim.x + threadIdx.x;
    if (t >= N) return;
    int o = off[t];
    csr[o] = t;
    cursor[t] = o + 1;
}

__global__ void csr_fill_kernel(const int* __restrict__ esrc, const int* __restrict__ edst,
                                int* __restrict__ cursor, int* __restrict__ csr, int E)
{
    int t = blockIdx.x * blockDim.x + threadIdx.x;
    if (t >= E) return;
    int d = __ldg(edst + t);
    int pos = atomicAdd(cursor + d, 1);
    csr[pos] = __ldg(esrc + t);
}

// ---------------- attention logit halves (fp16 hp) ----------------
__global__ void prep_kernel(const unsigned* __restrict__ hpP,
                            const float* __restrict__ a_src, const float* __restrict__ a_dst,
                            float* __restrict__ s_src, float* __restrict__ s_dst, int N)
{
    int t = blockIdx.x * blockDim.x + threadIdx.x;
    if (t >= N * 8) return;
    int n = t >> 3, h = t & 7;
    const uint4* hv = (const uint4*)(hpP + (size_t)n * 128 + h * 16);
    const float* av = a_src + h * 32;
    const float* bv = a_dst + h * 32;
    float ss = 0.f, sd = 0.f;
#pragma unroll
    for (int i = 0; i < 4; ++i) {
        uint4 q = hv[i];
        const unsigned* qq = (const unsigned*)&q;
#pragma unroll
        for (int j = 0; j < 4; ++j) {
            float2 f = unpackh2(qq[j]);
            int idx = i * 8 + j * 2;
            ss += f.x * av[idx] + f.y * av[idx + 1];
            sd += f.x * bv[idx] + f.y * bv[idx + 1];
        }
    }
    s_src[t] = ss;
    s_dst[t] = sd;
}

// ---------------- warp-per-node gather aggregation (fp16 hp, unroll-4) ----------------
__global__ void aggregate_kernel(const int* __restrict__ off, const int* __restrict__ csr,
                                 const float* __restrict__ s_src, const float* __restrict__ s_dst,
                                 const unsigned* __restrict__ hpP, const float* __restrict__ bias,
                                 float* __restrict__ outF,
                                 unsigned* __restrict__ outH, unsigned* __restrict__ outL, int N)
{
    int gt = blockIdx.x * blockDim.x + threadIdx.x;
    int w = gt >> 5, lane = gt & 31;
    if (w >= N) return;
    int beg = __ldg(off + w), end = __ldg(off + w + 1);
    int h = lane >> 2;
    float sd = __ldg(s_dst + w * 8 + h);

    float acc[8];
#pragma unroll
    for (int i = 0; i < 8; ++i) acc[i] = 0.f;
    float den = 0.f;

    int e = beg;
    for (; e + 4 <= end; e += 4) {
        int s0 = __ldg(csr + e),     s1 = __ldg(csr + e + 1);
        int s2 = __ldg(csr + e + 2), s3 = __ldg(csr + e + 3);
        float l0 = __ldg(s_src + s0 * 8 + h), l1 = __ldg(s_src + s1 * 8 + h);
        float l2 = __ldg(s_src + s2 * 8 + h), l3 = __ldg(s_src + s3 * 8 + h);
        uint4 q0 = __ldg((const uint4*)(hpP + (size_t)s0 * 128) + lane);
        uint4 q1 = __ldg((const uint4*)(hpP + (size_t)s1 * 128) + lane);
        uint4 q2 = __ldg((const uint4*)(hpP + (size_t)s2 * 128) + lane);
        uint4 q3 = __ldg((const uint4*)(hpP + (size_t)s3 * 128) + lane);
        l0 += sd; l0 = (l0 > 0.f) ? l0 : 0.2f * l0;
        l1 += sd; l1 = (l1 > 0.f) ? l1 : 0.2f * l1;
        l2 += sd; l2 = (l2 > 0.f) ? l2 : 0.2f * l2;
        l3 += sd; l3 = (l3 > 0.f) ? l3 : 0.2f * l3;
        float x0 = __expf(l0), x1 = __expf(l1), x2 = __expf(l2), x3 = __expf(l3);
        den += (x0 + x1) + (x2 + x3);
        const unsigned* a0 = (const unsigned*)&q0;
        const unsigned* a1 = (const unsigned*)&q1;
        const unsigned* a2 = (const unsigned*)&q2;
        const unsigned* a3 = (const unsigned*)&q3;
#pragma unroll
        for (int j = 0; j < 4; ++j) {
            float2 f0 = unpackh2(a0[j]), f1 = unpackh2(a1[j]);
            float2 f2 = unpackh2(a2[j]), f3 = unpackh2(a3[j]);
            acc[2 * j]     += x0 * f0.x + x1 * f1.x + x2 * f2.x + x3 * f3.x;
            acc[2 * j + 1] += x0 * f0.y + x1 * f1.y + x2 * f2.y + x3 * f3.y;
        }
    }
    for (; e < end; ++e) {
        int s = __ldg(csr + e);
        float ee = __ldg(s_src + s * 8 + h) + sd;
        ee = (ee > 0.f) ? ee : 0.2f * ee;
        float ex = __expf(ee);
        den += ex;
        uint4 q = __ldg((const uint4*)(hpP + (size_t)s * 128) + lane);
        const unsigned* a0 = (const unsigned*)&q;
#pragma unroll
        for (int j = 0; j < 4; ++j) {
            float2 f = unpackh2(a0[j]);
            acc[2 * j]     += ex * f.x;
            acc[2 * j + 1] += ex * f.y;
        }
    }
    float inv = 1.f / den;
    const float4* bb = (const float4*)(bias + lane * 8);
    float4 b0 = bb[0], b1 = bb[1];
    float o[8] = { acc[0] * inv + b0.x, acc[1] * inv + b0.y, acc[2] * inv + b0.z, acc[3] * inv + b0.w,
                   acc[4] * inv + b1.x, acc[5] * inv + b1.y, acc[6] * inv + b1.z, acc[7] * inv + b1.w };
#pragma unroll
    for (int i = 0; i < 8; ++i) o[i] = (o[i] > 0.f) ? o[i] : expm1f(o[i]);  // elu
    if (outF) {
        float4* ov = (float4*)(outF + (size_t)w * 256 + lane * 8);
        ov[0] = make_float4(o[0], o[1], o[2], o[3]);
        ov[1] = make_float4(o[4], o[5], o[6], o[7]);
    }
#pragma unroll
    for (int j = 0; j < 4; ++j) {
        unsigned hh, ll;
        split2(o[2 * j], o[2 * j + 1], hh, ll);
        size_t oi = (size_t)w * 128 + lane * 4 + j;
        outH[oi] = hh; outL[oi] = ll;
    }
}

// ---------------- semantic score ----------------
__global__ void score_kernel(const float* __restrict__ t128, const float* __restrict__ W2,
                             float* __restrict__ scores, int N, int p)
{
    int gt = blockIdx.x * blockDim.x + threadIdx.x;
    int n = gt >> 5, lane = gt & 31;
    if (n >= N) return;
    const float* r = t128 + (size_t)n * 128;
    float v = r[lane] * W2[lane] + r[lane + 32] * W2[lane + 32]
            + r[lane + 64] * W2[lane + 64] + r[lane + 96] * W2[lane + 96];
#pragma unroll
    for (int o = 16; o > 0; o >>= 1) v += __shfl_xor_sync(0xffffffffu, v, o);
    if (lane == 0) scores[n * 3 + p] = v;
}

// ---------------- softmax over 3 metapaths + weighted sum (split output) ----------------
__global__ void combine_kernel(const float* __restrict__ e0, const float* __restrict__ e1,
                               const float* __restrict__ e2, const float* __restrict__ scores,
                               unsigned* __restrict__ zH, unsigned* __restrict__ zL, int N)
{
    int t = blockIdx.x * blockDim.x + threadIdx.x;
    if (t >= N * 64) return;
    int n = t >> 6, q = t & 63;
    float s0 = scores[n * 3], s1 = scores[n * 3 + 1], s2 = scores[n * 3 + 2];
    float m = fmaxf(s0, fmaxf(s1, s2));
    float w0 = __expf(s0 - m), w1 = __expf(s1 - m), w2 = __expf(s2 - m);
    float inv = 1.f / (w0 + w1 + w2);
    w0 *= inv; w1 *= inv; w2 *= inv;
    size_t offi = (size_t)n * 256 + q * 4;
    float4 a = *(const float4*)(e0 + offi);
    float4 b = *(const float4*)(e1 + offi);
    float4 c = *(const float4*)(e2 + offi);
    float ox = w0 * a.x + w1 * b.x + w2 * c.x;
    float oy = w0 * a.y + w1 * b.y + w2 * c.y;
    float oz = w0 * a.z + w1 * b.z + w2 * c.z;
    float ow = w0 * a.w + w1 * b.w + w2 * c.w;
    unsigned h, l;
    size_t zi = (size_t)n * 128 + q * 2;
    split2(ox, oy, h, l); zH[zi] = h;     zL[zi] = l;
    split2(oz, ow, h, l); zH[zi + 1] = h; zL[zi + 1] = l;
}

// ---------------- classifier head ----------------
__global__ void logits_kernel(const float* __restrict__ hcls, const float* __restrict__ W2,
                              const float* __restrict__ b2, float* __restrict__ out, int N)
{
    int gt = blockIdx.x * blockDim.x + threadIdx.x;
    int n = gt >> 5, lane = gt & 31;
    if (n >= N) return;
    const float* r = hcls + (size_t)n * 128;
    float x0 = r[lane], x1 = r[lane + 32], x2 = r[lane + 64], x3 = r[lane + 96];
    float s0 = x0 * W2[lane * 2]            + x1 * W2[(lane + 32) * 2]
             + x2 * W2[(lane + 64) * 2]     + x3 * W2[(lane + 96) * 2];
    float s1 = x0 * W2[lane * 2 + 1]        + x1 * W2[(lane + 32) * 2 + 1]
             + x2 * W2[(lane + 64) * 2 + 1] + x3 * W2[(lane + 96) * 2 + 1];
#pragma unroll
    for (int o = 16; o > 0; o >>= 1) {
        s0 += __shfl_xor_sync(0xffffffffu, s0, o);
        s1 += __shfl_xor_sync(0xffffffffu, s1, o);
    }
    if (lane == 0) {
        out[n * 2]     = s0 + b2[0];
        out[n * 2 + 1] = s1 + b2[1];
    }
}

// ---------------- launch ----------------
extern "C" void kernel_launch(void* const* d_in, const int* in_sizes, int n_in,
                              void* d_out, int out_size)
{
    const float* x        = (const float*)d_in[0];
    const int*   edges    = (const int*)d_in[1];
    const float* proj_W   = (const float*)d_in[2];
    const float* proj_b   = (const float*)d_in[3];
    const float* gat_W    = (const float*)d_in[4];
    const float* gat_asrc = (const float*)d_in[5];
    const float* gat_adst = (const float*)d_in[6];
    const float* gat_b    = (const float*)d_in[7];
    const float* sem_W1   = (const float*)d_in[8];
    const float* sem_b1   = (const float*)d_in[9];
    const float* sem_W2   = (const float*)d_in[10];
    const float* cls_W1   = (const float*)d_in[11];
    const float* cls_b1   = (const float*)d_in[12];
    const float* cls_W2   = (const float*)d_in[13];
    const float* cls_b2   = (const float*)d_in[14];
    float* out = (float*)d_out;

    const int N = in_sizes[0] / 128;  // 50000
    const int E = in_sizes[1] / 6;    // 800000

    unsigned *xH, *xL, *h0H, *h0L, *hpP, *hH, *hL, *embH, *embL, *zH, *zL, *wH, *wL;
    float *emb, *ssrc, *sdst, *tbuf, *scores, *hcls;
    int *deg, *off, *cursor, *csr, *partials;
    cudaGetSymbolAddress((void**)&xH,   g_xH);   cudaGetSymbolAddress((void**)&xL,   g_xL);
    cudaGetSymbolAddress((void**)&h0H,  g_h0H);  cudaGetSymbolAddress((void**)&h0L,  g_h0L);
    cudaGetSymbolAddress((void**)&hpP,  g_hpP);
    cudaGetSymbolAddress((void**)&hH,   g_hH);   cudaGetSymbolAddress((void**)&hL,   g_hL);
    cudaGetSymbolAddress((void**)&embH, g_embH); cudaGetSymbolAddress((void**)&embL, g_embL);
    cudaGetSymbolAddress((void**)&zH,   g_zH);   cudaGetSymbolAddress((void**)&zL,   g_zL);
    cudaGetSymbolAddress((void**)&wH,   g_wH);   cudaGetSymbolAddress((void**)&wL,   g_wL);
    cudaGetSymbolAddress((void**)&emb,  g_emb);
    cudaGetSymbolAddress((void**)&ssrc, g_ssrc); cudaGetSymbolAddress((void**)&sdst, g_sdst);
    cudaGetSymbolAddress((void**)&tbuf, g_t);
    cudaGetSymbolAddress((void**)&scores, g_scores);
    cudaGetSymbolAddress((void**)&hcls, g_hcls);
    cudaGetSymbolAddress((void**)&deg,  g_deg);  cudaGetSymbolAddress((void**)&off, g_off);
    cudaGetSymbolAddress((void**)&cursor, g_cursor);
    cudaGetSymbolAddress((void**)&csr,  g_csr);  cudaGetSymbolAddress((void**)&partials, g_partials);

    static bool s_init = false;
    static cudaStream_t st1, st2;
    static cudaEvent_t evRoot, evJ1, evJ2;
    if (!s_init) {
        cudaStreamCreateWithFlags(&st1, cudaStreamNonBlocking);
        cudaStreamCreateWithFlags(&st2, cudaStreamNonBlocking);
        cudaEventCreateWithFlags(&evRoot, cudaEventDisableTiming);
        cudaEventCreateWithFlags(&evJ1, cudaEventDisableTiming);
        cudaEventCreateWithFlags(&evJ2, cudaEventDisableTiming);
        s_init = true;
    }
    cudaStream_t streams[3] = { (cudaStream_t)0, st1, st2 };

    const int nb1024 = (N + 1023) / 1024;
    const int OFF_PROJ = 0;
    const int OFF_GAT  = 16384;
    const int OFF_SEM  = 212992;
    const int OFF_CLS  = 229376;

    // --- stream 0: weight splits, x split, proj GEMM ---
    split_pairs_kernel<<<(N * 64 + 255) / 256, 256>>>(x, xH, xL, N * 64);
    split_w_kernel<<<(64 * 256 + 255) / 256, 256>>>(proj_W, wH + OFF_PROJ, wL + OFF_PROJ, 64, 256);
    for (int i = 0; i < 6; ++i)
        split_w_kernel<<<(128 * 256 + 255) / 256, 256>>>(gat_W + (size_t)i * 65536,
            wH + OFF_GAT + i * 32768, wL + OFF_GAT + i * 32768, 128, 256);
    split_w_kernel<<<(128 * 128 + 255) / 256, 256>>>(sem_W1, wH + OFF_SEM, wL + OFF_SEM, 128, 128);
    split_w_kernel<<<(128 * 128 + 255) / 256, 256>>>(cls_W1, wH + OFF_CLS, wL + OFF_CLS, 128, 128);

    {   // h0 = x @ proj_W + proj_b -> bf16 split pairs
        dim3 grid(4, (N + 127) / 128);
        gemm_bf16_kernel<<<grid, 256>>>(xH, xL, wH + OFF_PROJ, wL + OFF_PROJ, proj_b,
                                        nullptr, h0H, h0L, nullptr, N, 256, 64, 0);
    }
    cudaEventRecord(evRoot, 0);
    cudaStreamWaitEvent(st1, evRoot, 0);
    cudaStreamWaitEvent(st2, evRoot, 0);

    // --- per-metapath pipelines on 3 streams ---
    for (int p = 0; p < 3; ++p) {
        cudaStream_t S = streams[p];
        const int* esrc = edges + (size_t)p * 2 * E;
        const int* edst = esrc + E;
        int* deg_p = deg + (size_t)p * NN;
        int* off_p = off + (size_t)p * (NN + 1);
        int* cur_p = cursor + (size_t)p * NN;
        int* csr_p = csr + (size_t)p * (EE + NN);
        int* par_p = partials + p * 64;
        unsigned* hpP_p = hpP + (size_t)p * NN * 128;
        float* ss_p = ssrc + (size_t)p * NN * 8;
        float* sd_p = sdst + (size_t)p * NN * 8;
        unsigned* hH_p = hH + (size_t)p * NN * 128;
        unsigned* hL_p = hL + (size_t)p * NN * 128;
        unsigned* eH_p = embH + (size_t)p * NN * 128;
        unsigned* eL_p = embL + (size_t)p * NN * 128;
        float* emb_p = emb + (size_t)p * NN * 256;
        float* t_p = tbuf + (size_t)p * NN * 128;

        deg_init_kernel<<<(N + 255) / 256, 256, 0, S>>>(deg_p, N);
        deg_count_kernel<<<(E + 255) / 256, 256, 0, S>>>(edst, deg_p, E);
        scan_local_kernel<<<nb1024, 1024, 0, S>>>(deg_p, off_p, par_p, N);
        scan_partials_kernel<<<1, 64, 0, S>>>(par_p, nb1024, off_p, N);
        scan_add_kernel<<<nb1024 * 4, 256, 0, S>>>(off_p, par_p, N);
        csr_init_kernel<<<(N + 255) / 256, 256, 0, S>>>(off_p, cur_p, csr_p, N);
        csr_fill_kernel<<<(E + 255) / 256, 256, 0, S>>>(esrc, edst, cur_p, csr_p, E);

        for (int l = 0; l < 2; ++l) {
            const unsigned* AHc = (l == 0) ? h0H : hH_p;
            const unsigned* ALc = (l == 0) ? h0L : hL_p;
            const unsigned* WHc = wH + OFF_GAT + (p * 2 + l) * 32768;
            const unsigned* WLc = wL + OFF_GAT + (p * 2 + l) * 32768;
            const float* as_ = gat_asrc + (size_t)(p * 2 + l) * 256;
            const float* ad_ = gat_adst + (size_t)(p * 2 + l) * 256;
            const float* bb  = gat_b    + (size_t)(p * 2 + l) * 256;

            dim3 grid(4, (N + 127) / 128);
            gemm_bf16_kernel<<<grid, 256, 0, S>>>(AHc, ALc, WHc, WLc, nullptr,
                                                  nullptr, nullptr, nullptr, hpP_p, N, 256, 128, 0);
            prep_kernel<<<(N * 8 + 255) / 256, 256, 0, S>>>(hpP_p, as_, ad_, ss_p, sd_p, N);
            if (l == 0)
                aggregate_kernel<<<(N * 32 + 255) / 256, 256, 0, S>>>(
                    off_p, csr_p, ss_p, sd_p, hpP_p, bb, nullptr, hH_p, hL_p, N);
            else
                aggregate_kernel<<<(N * 32 + 255) / 256, 256, 0, S>>>(
                    off_p, csr_p, ss_p, sd_p, hpP_p, bb, emb_p, eH_p, eL_p, N);
        }
        {
            dim3 grid(2, (N + 127) / 128);
            gemm_bf16_kernel<<<grid, 256, 0, S>>>(eH_p, eL_p, wH + OFF_SEM, wL + OFF_SEM, sem_b1,
                                                  t_p, nullptr, nullptr, nullptr, N, 128, 128, 1);
        }
        score_kernel<<<(N * 32 + 255) / 256, 256, 0, S>>>(t_p, sem_W2, scores, N, p);
    }
    cudaEventRecord(evJ1, st1);
    cudaEventRecord(evJ2, st2);
    cudaStreamWaitEvent((cudaStream_t)0, evJ1, 0);
    cudaStreamWaitEvent((cudaStream_t)0, evJ2, 0);

    // --- join: combine + classifier on stream 0 ---
    combine_kernel<<<(N * 64 + 255) / 256, 256>>>(
        emb, emb + (size_t)NN * 256, emb + (size_t)2 * NN * 256, scores, zH, zL, N);
    {
        dim3 grid(2, (N + 127) / 128);
        gemm_bf16_kernel<<<grid, 256>>>(zH, zL, wH + OFF_CLS, wL + OFF_CLS, cls_b1,
                                        hcls, nullptr, nullptr, nullptr, N, 128, 128, 2);
    }
    logits_kernel<<<(N * 32 + 255) / 256, 256>>>(hcls, cls_W2, cls_b2, out, N);
}

// round 14
// speedup vs baseline: 2.6214x; 1.0839x over previous
#include <cuda_runtime.h>
#include <cuda_bf16.h>
#include <cuda_fp16.h>
#include <math.h>

#define NN 50000
#define EE 800000

// ---------------- scratch ----------------
__device__ __align__(16) unsigned g_xH[NN * 64],  g_xL[NN * 64];
__device__ __align__(16) unsigned g_h0H[NN * 128], g_h0L[NN * 128];
__device__ __align__(16) unsigned g_hpP[3ll * NN * 128];              // hp packed fp16
__device__ __align__(16) unsigned g_hH[3ll * NN * 128], g_hL[3ll * NN * 128];
__device__ __align__(16) float    g_emb[3ll * NN * 256];
__device__ __align__(16) unsigned g_embH[3ll * NN * 128], g_embL[3ll * NN * 128];
__device__ __align__(16) unsigned g_zH[NN * 128], g_zL[NN * 128];
__device__ __align__(16) float    g_ssrc[3ll * NN * 8], g_sdst[3ll * NN * 8];
__device__ __align__(16) float    g_t[3ll * NN * 128];
__device__ __align__(16) float    g_scores[NN * 3];
__device__ __align__(16) float    g_hcls[NN * 128];
__device__ __align__(16) unsigned g_wH[245760], g_wL[245760];
__device__ int g_deg[3ll * NN];
__device__ int g_off[3ll * (NN + 1)];
__device__ int g_cursor[3ll * NN];
__device__ int g_csr[3ll * (EE + NN)];
__device__ int g_partials[3 * 64];

// ---------------- helpers ----------------
__device__ __forceinline__ void split2(float a, float b, unsigned& hi, unsigned& lo)
{
    __nv_bfloat16 ah = __float2bfloat16_rn(a);
    __nv_bfloat16 bh = __float2bfloat16_rn(b);
    __nv_bfloat16 al = __float2bfloat16_rn(a - __bfloat162float(ah));
    __nv_bfloat16 bl = __float2bfloat16_rn(b - __bfloat162float(bh));
    __nv_bfloat162 h2 = __halves2bfloat162(ah, bh);
    __nv_bfloat162 l2 = __halves2bfloat162(al, bl);
    hi = *reinterpret_cast<unsigned*>(&h2);
    lo = *reinterpret_cast<unsigned*>(&l2);
}

__device__ __forceinline__ unsigned packh2(float a, float b)
{
    __half2 h = __floats2half2_rn(a, b);
    return *reinterpret_cast<unsigned*>(&h);
}

__device__ __forceinline__ float2 unpackh2(unsigned u)
{
    __half2 h = *reinterpret_cast<__half2*>(&u);
    return __half22float2(h);
}

__device__ __forceinline__ void mma_bf16(float (&d)[4], const unsigned (&a)[4], const unsigned (&b)[2])
{
    asm volatile("mma.sync.aligned.m16n8k16.row.col.f32.bf16.bf16.f32 "
        "{%0,%1,%2,%3}, {%4,%5,%6,%7}, {%8,%9}, {%0,%1,%2,%3};"
        : "+f"(d[0]), "+f"(d[1]), "+f"(d[2]), "+f"(d[3])
        : "r"(a[0]), "r"(a[1]), "r"(a[2]), "r"(a[3]), "r"(b[0]), "r"(b[1]));
}

// ---------------- split kernels ----------------
__global__ void split_pairs_kernel(const float* __restrict__ in, unsigned* __restrict__ oh,
                                   unsigned* __restrict__ ol, int npairs)
{
    int t = blockIdx.x * blockDim.x + threadIdx.x;
    if (t >= npairs) return;
    unsigned h, l;
    split2(in[2 * t], in[2 * t + 1], h, l);
    oh[t] = h; ol[t] = l;
}

__global__ void split_w_kernel(const float* __restrict__ W, unsigned* __restrict__ oh,
                               unsigned* __restrict__ ol, int K2, int N)
{
    int t = blockIdx.x * blockDim.x + threadIdx.x;
    if (t >= K2 * N) return;
    int kp = t / N, n = t - kp * N;
    unsigned h, l;
    split2(W[(size_t)(2 * kp) * N + n], W[(size_t)(2 * kp + 1) * N + n], h, l);
    oh[t] = h; ol[t] = l;
}

// ---------------- bf16x3 tensor-core GEMM, double-buffered ----------------
// A [M][K2] / B [K2][N] packed bf16 pairs. Outputs: fp32 / bf16 pairs / packed fp16.
// If aSrc != nullptr (requires N==256, grid.x==4): also emits per-(row,head) attention
// logit halves sSrc/sDst ([M][8]) from the raw (pre-bias) GEMM values.
__global__ void gemm_bf16_kernel(const unsigned* __restrict__ AH, const unsigned* __restrict__ AL,
                                 const unsigned* __restrict__ BH, const unsigned* __restrict__ BL,
                                 const float* __restrict__ bias,
                                 float* __restrict__ outF,
                                 unsigned* __restrict__ outH, unsigned* __restrict__ outL,
                                 unsigned* __restrict__ outP,
                                 const float* __restrict__ aSrc, const float* __restrict__ aDst,
                                 float* __restrict__ sSrc, float* __restrict__ sDst,
                                 int M, int N, int K2, int act)
{
    __shared__ unsigned AsH[2][128][12], AsL[2][128][12];
    __shared__ unsigned BsH[2][64][12],  BsL[2][64][12];

    const int tid = threadIdx.x;
    const int lane = tid & 31;
    const int warp = tid >> 5;
    const int wm = warp & 3, wn = warp >> 2;
    const int rowBase = blockIdx.y * 128;
    const int colBase = blockIdx.x * 64;
    const int g = lane >> 2, t = lane & 3;

    float acc[2][4][4];
#pragma unroll
    for (int mt = 0; mt < 2; ++mt)
#pragma unroll
        for (int nt = 0; nt < 4; ++nt)
#pragma unroll
            for (int i = 0; i < 4; ++i) acc[mt][nt][i] = 0.f;

    const int am = tid >> 1;
    const int aq = (tid & 1) * 4;
    const int bn = tid & 63;
    const int bkp = tid >> 6;
    const int gr = rowBase + am;
    const bool aval = (gr < M);
    const int T = K2 >> 3;

    uint4 rAH = make_uint4(0,0,0,0), rAL = make_uint4(0,0,0,0);
    unsigned rB0, rB1, rB2, rB3;

    // preload tile 0
    {
        if (aval) {
            rAH = *(const uint4*)(AH + (size_t)gr * K2 + aq);
            rAL = *(const uint4*)(AL + (size_t)gr * K2 + aq);
        }
        size_t o0 = (size_t)bkp * N + colBase + bn;
        size_t o1 = (size_t)(bkp + 4) * N + colBase + bn;
        rB0 = BH[o0]; rB1 = BL[o0]; rB2 = BH[o1]; rB3 = BL[o1];
        *(uint4*)&AsH[0][am][aq] = rAH;
        *(uint4*)&AsL[0][am][aq] = rAL;
        BsH[0][bn][bkp] = rB0;     BsL[0][bn][bkp] = rB1;
        BsH[0][bn][bkp + 4] = rB2; BsL[0][bn][bkp + 4] = rB3;
    }
    __syncthreads();

    for (int kt = 0; kt < T; ++kt) {
        const int cur = kt & 1;
        if (kt + 1 < T) {   // issue next-tile global loads before MMA
            int kp0 = (kt + 1) * 8;
            if (aval) {
                rAH = *(const uint4*)(AH + (size_t)gr * K2 + kp0 + aq);
                rAL = *(const uint4*)(AL + (size_t)gr * K2 + kp0 + aq);
            }
            size_t o0 = (size_t)(kp0 + bkp) * N + colBase + bn;
            size_t o1 = (size_t)(kp0 + bkp + 4) * N + colBase + bn;
            rB0 = BH[o0]; rB1 = BL[o0]; rB2 = BH[o1]; rB3 = BL[o1];
        }

        unsigned aH[2][4], aL[2][4], bH[4][2], bL[4][2];
#pragma unroll
        for (int mt = 0; mt < 2; ++mt) {
            int mr = wm * 32 + mt * 16;
            aH[mt][0] = AsH[cur][mr + g][t];     aH[mt][1] = AsH[cur][mr + 8 + g][t];
            aH[mt][2] = AsH[cur][mr + g][t + 4]; aH[mt][3] = AsH[cur][mr + 8 + g][t + 4];
            aL[mt][0] = AsL[cur][mr + g][t];     aL[mt][1] = AsL[cur][mr + 8 + g][t];
            aL[mt][2] = AsL[cur][mr + g][t + 4]; aL[mt][3] = AsL[cur][mr + 8 + g][t + 4];
        }
#pragma unroll
        for (int nt = 0; nt < 4; ++nt) {
            int nr = wn * 32 + nt * 8;
            bH[nt][0] = BsH[cur][nr + g][t]; bH[nt][1] = BsH[cur][nr + g][t + 4];
            bL[nt][0] = BsL[cur][nr + g][t]; bL[nt][1] = BsL[cur][nr + g][t + 4];
        }
#pragma unroll
        for (int mt = 0; mt < 2; ++mt)
#pragma unroll
            for (int nt = 0; nt < 4; ++nt) {
                mma_bf16(acc[mt][nt], aH[mt], bH[nt]);
                mma_bf16(acc[mt][nt], aL[mt], bH[nt]);
                mma_bf16(acc[mt][nt], aH[mt], bL[nt]);
            }

        if (kt + 1 < T) {   // store next tile to the other buffer (safe: last read 1 sync ago)
            const int nxt = 1 - cur;
            *(uint4*)&AsH[nxt][am][aq] = rAH;
            *(uint4*)&AsL[nxt][am][aq] = rAL;
            BsH[nxt][bn][bkp] = rB0;     BsL[nxt][bn][bkp] = rB1;
            BsH[nxt][bn][bkp + 4] = rB2; BsL[nxt][bn][bkp + 4] = rB3;
            __syncthreads();
        }
    }

    // epilogue (+ optional fused attention-logit reduction)
    float pS[2][2] = {{0.f, 0.f}, {0.f, 0.f}};
    float pD[2][2] = {{0.f, 0.f}, {0.f, 0.f}};
    const bool doS = (aSrc != nullptr);

#pragma unroll
    for (int mt = 0; mt < 2; ++mt) {
#pragma unroll
        for (int nt = 0; nt < 4; ++nt) {
            int c = colBase + wn * 32 + nt * 8 + 2 * t;
            float b0 = bias ? bias[c] : 0.f;
            float b1 = bias ? bias[c + 1] : 0.f;
#pragma unroll
            for (int half = 0; half < 2; ++half) {
                int r = rowBase + wm * 32 + mt * 16 + g + half * 8;
                float v0 = acc[mt][nt][half * 2 + 0] + b0;
                float v1 = acc[mt][nt][half * 2 + 1] + b1;
                if (act == 1) { v0 = tanhf(v0); v1 = tanhf(v1); }
                else if (act == 2) { v0 = fmaxf(v0, 0.f); v1 = fmaxf(v1, 0.f); }
                if (doS) {
                    pS[mt][half] += v0 * aSrc[c] + v1 * aSrc[c + 1];
                    pD[mt][half] += v0 * aDst[c] + v1 * aDst[c + 1];
                }
                if (r < M) {
                    if (outF) *(float2*)(outF + (size_t)r * N + c) = make_float2(v0, v1);
                    if (outP) outP[(size_t)r * (N >> 1) + (c >> 1)] = packh2(v0, v1);
                    if (outH) {
                        unsigned h, l;
                        split2(v0, v1, h, l);
                        size_t oi = (size_t)r * (N >> 1) + (c >> 1);
                        outH[oi] = h; outL[oi] = l;
                    }
                }
            }
        }
    }
    if (doS) {
        int head = blockIdx.x * 2 + wn;   // N==256, grid.x==4
#pragma unroll
        for (int mt = 0; mt < 2; ++mt)
#pragma unroll
            for (int half = 0; half < 2; ++half) {
                float s = pS[mt][half], d = pD[mt][half];
                s += __shfl_xor_sync(0xffffffffu, s, 1);
                s += __shfl_xor_sync(0xffffffffu, s, 2);
                d += __shfl_xor_sync(0xffffffffu, d, 1);
                d += __shfl_xor_sync(0xffffffffu, d, 2);
                int r = rowBase + wm * 32 + mt * 16 + g + half * 8;
                if (t == 0 && r < M) {
                    sSrc[r * 8 + head] = s;
                    sDst[r * 8 + head] = d;
                }
            }
    }
}

// ---------------- CSR build ----------------
__global__ void deg_init_kernel(int* __restrict__ deg, int N)
{
    int t = blockIdx.x * blockDim.x + threadIdx.x;
    if (t < N) deg[t] = 1;
}

__global__ void deg_count_kernel(const int* __restrict__ edst, int* __restrict__ deg, int E)
{
    int t = blockIdx.x * blockDim.x + threadIdx.x;
    if (t < E) atomicAdd(deg + __ldg(edst + t), 1);
}

__global__ void scan_local_kernel(const int* __restrict__ deg, int* __restrict__ off,
                                  int* __restrict__ partials, int N)
{
    __shared__ int sm[1024];
    int b = blockIdx.x, tid = threadIdx.x;
    int i = b * 1024 + tid;
    int v = (i < N) ? deg[i] : 0;
    sm[tid] = v;
    __syncthreads();
    for (int o = 1; o < 1024; o <<= 1) {
        int x = (tid >= o) ? sm[tid - o] : 0;
        __syncthreads();
        sm[tid] += x;
        __syncthreads();
    }
    if (i < N) off[i] = sm[tid] - v;
    if (tid == 1023) partials[b] = sm[1023];
}

__global__ void scan_partials_kernel(int* __restrict__ partials, int nb,
                                     int* __restrict__ off, int N)
{
    __shared__ int sm[64];
    int tid = threadIdx.x;
    int v = (tid < nb) ? partials[tid] : 0;
    sm[tid] = v;
    __syncthreads();
    for (int o = 1; o < 64; o <<= 1) {
        int x = (tid >= o) ? sm[tid - o] : 0;
        __syncthreads();
        sm[tid] += x;
        __syncthreads();
    }
    if (tid < nb) partials[tid] = sm[tid] - v;
    if (tid == 63) off[N] = sm[63];
}

__global__ void scan_add_kernel(int* __restrict__ off, const int* __restrict__ partials, int N)
{
    int i = blockIdx.x * blockDim.x + threadIdx.x;
    if (i < N) off[i] += partials[blockIdx.x >> 2];
}

__global__ void csr_init_kernel(const int* __restrict__ off, int* __restrict__ cursor,
                                int* __restrict__ csr, int N)
{
    int t = blockIdx.x * blockDim.x + threadIdx.x;
    if (t >= N) return;
    int o = off[t];
    csr[o] = t;
    cursor[t] = o + 1;
}

__global__ void csr_fill_kernel(const int* __restrict__ esrc, const int* __restrict__ edst,
                                int* __restrict__ cursor, int* __restrict__ csr, int E)
{
    int t = blockIdx.x * blockDim.x + threadIdx.x;
    if (t >= E) return;
    int d = __ldg(edst + t);
    int pos = atomicAdd(cursor + d, 1);
    csr[pos] = __ldg(esrc + t);
}

// ---------------- warp-per-node gather aggregation (fp16 hp, unroll-4) ----------------
__global__ void aggregate_kernel(const int* __restrict__ off, const int* __restrict__ csr,
                                 const float* __restrict__ s_src, const float* __restrict__ s_dst,
                                 const unsigned* __restrict__ hpP, const float* __restrict__ bias,
                                 float* __restrict__ outF,
                                 unsigned* __restrict__ outH, unsigned* __restrict__ outL, int N)
{
    int gt = blockIdx.x * blockDim.x + threadIdx.x;
    int w = gt >> 5, lane = gt & 31;
    if (w >= N) return;
    int beg = __ldg(off + w), end = __ldg(off + w + 1);
    int h = lane >> 2;
    float sd = __ldg(s_dst + w * 8 + h);

    float acc[8];
#pragma unroll
    for (int i = 0; i < 8; ++i) acc[i] = 0.f;
    float den = 0.f;

    int e = beg;
    for (; e + 4 <= end; e += 4) {
        int s0 = __ldg(csr + e),     s1 = __ldg(csr + e + 1);
        int s2 = __ldg(csr + e + 2), s3 = __ldg(csr + e + 3);
        float l0 = __ldg(s_src + s0 * 8 + h), l1 = __ldg(s_src + s1 * 8 + h);
        float l2 = __ldg(s_src + s2 * 8 + h), l3 = __ldg(s_src + s3 * 8 + h);
        uint4 q0 = __ldg((const uint4*)(hpP + (size_t)s0 * 128) + lane);
        uint4 q1 = __ldg((const uint4*)(hpP + (size_t)s1 * 128) + lane);
        uint4 q2 = __ldg((const uint4*)(hpP + (size_t)s2 * 128) + lane);
        uint4 q3 = __ldg((const uint4*)(hpP + (size_t)s3 * 128) + lane);
        l0 += sd; l0 = (l0 > 0.f) ? l0 : 0.2f * l0;
        l1 += sd; l1 = (l1 > 0.f) ? l1 : 0.2f * l1;
        l2 += sd; l2 = (l2 > 0.f) ? l2 : 0.2f * l2;
        l3 += sd; l3 = (l3 > 0.f) ? l3 : 0.2f * l3;
        float x0 = __expf(l0), x1 = __expf(l1), x2 = __expf(l2), x3 = __expf(l3);
        den += (x0 + x1) + (x2 + x3);
        const unsigned* a0 = (const unsigned*)&q0;
        const unsigned* a1 = (const unsigned*)&q1;
        const unsigned* a2 = (const unsigned*)&q2;
        const unsigned* a3 = (const unsigned*)&q3;
#pragma unroll
        for (int j = 0; j < 4; ++j) {
            float2 f0 = unpackh2(a0[j]), f1 = unpackh2(a1[j]);
            float2 f2 = unpackh2(a2[j]), f3 = unpackh2(a3[j]);
            acc[2 * j]     += x0 * f0.x + x1 * f1.x + x2 * f2.x + x3 * f3.x;
            acc[2 * j + 1] += x0 * f0.y + x1 * f1.y + x2 * f2.y + x3 * f3.y;
        }
    }
    for (; e < end; ++e) {
        int s = __ldg(csr + e);
        float ee = __ldg(s_src + s * 8 + h) + sd;
        ee = (ee > 0.f) ? ee : 0.2f * ee;
        float ex = __expf(ee);
        den += ex;
        uint4 q = __ldg((const uint4*)(hpP + (size_t)s * 128) + lane);
        const unsigned* a0 = (const unsigned*)&q;
#pragma unroll
        for (int j = 0; j < 4; ++j) {
            float2 f = unpackh2(a0[j]);
            acc[2 * j]     += ex * f.x;
            acc[2 * j + 1] += ex * f.y;
        }
    }
    float inv = 1.f / den;
    const float4* bb = (const float4*)(bias + lane * 8);
    float4 b0 = bb[0], b1 = bb[1];
    float o[8] = { acc[0] * inv + b0.x, acc[1] * inv + b0.y, acc[2] * inv + b0.z, acc[3] * inv + b0.w,
                   acc[4] * inv + b1.x, acc[5] * inv + b1.y, acc[6] * inv + b1.z, acc[7] * inv + b1.w };
#pragma unroll
    for (int i = 0; i < 8; ++i) o[i] = (o[i] > 0.f) ? o[i] : expm1f(o[i]);  // elu
    if (outF) {
        float4* ov = (float4*)(outF + (size_t)w * 256 + lane * 8);
        ov[0] = make_float4(o[0], o[1], o[2], o[3]);
        ov[1] = make_float4(o[4], o[5], o[6], o[7]);
    }
#pragma unroll
    for (int j = 0; j < 4; ++j) {
        unsigned hh, ll;
        split2(o[2 * j], o[2 * j + 1], hh, ll);
        size_t oi = (size_t)w * 128 + lane * 4 + j;
        outH[oi] = hh; outL[oi] = ll;
    }
}

// ---------------- semantic score ----------------
__global__ void score_kernel(const float* __restrict__ t128, const float* __restrict__ W2,
                             float* __restrict__ scores, int N, int p)
{
    int gt = blockIdx.x * blockDim.x + threadIdx.x;
    int n = gt >> 5, lane = gt & 31;
    if (n >= N) return;
    const float* r = t128 + (size_t)n * 128;
    float v = r[lane] * W2[lane] + r[lane + 32] * W2[lane + 32]
            + r[lane + 64] * W2[lane + 64] + r[lane + 96] * W2[lane + 96];
#pragma unroll
    for (int o = 16; o > 0; o >>= 1) v += __shfl_xor_sync(0xffffffffu, v, o);
    if (lane == 0) scores[n * 3 + p] = v;
}

// ---------------- softmax over 3 metapaths + weighted sum ----------------
__global__ void combine_kernel(const float* __restrict__ e0, const float* __restrict__ e1,
                               const float* __restrict__ e2, const float* __restrict__ scores,
                               unsigned* __restrict__ zH, unsigned* __restrict__ zL, int N)
{
    int t = blockIdx.x * blockDim.x + threadIdx.x;
    if (t >= N * 64) return;
    int n = t >> 6, q = t & 63;
    float s0 = scores[n * 3], s1 = scores[n * 3 + 1], s2 = scores[n * 3 + 2];
    float m = fmaxf(s0, fmaxf(s1, s2));
    float w0 = __expf(s0 - m), w1 = __expf(s1 - m), w2 = __expf(s2 - m);
    float inv = 1.f / (w0 + w1 + w2);
    w0 *= inv; w1 *= inv; w2 *= inv;
    size_t offi = (size_t)n * 256 + q * 4;
    float4 a = *(const float4*)(e0 + offi);
    float4 b = *(const float4*)(e1 + offi);
    float4 c = *(const float4*)(e2 + offi);
    float ox = w0 * a.x + w1 * b.x + w2 * c.x;
    float oy = w0 * a.y + w1 * b.y + w2 * c.y;
    float oz = w0 * a.z + w1 * b.z + w2 * c.z;
    float ow = w0 * a.w + w1 * b.w + w2 * c.w;
    unsigned h, l;
    size_t zi = (size_t)n * 128 + q * 2;
    split2(ox, oy, h, l); zH[zi] = h;     zL[zi] = l;
    split2(oz, ow, h, l); zH[zi + 1] = h; zL[zi + 1] = l;
}

// ---------------- classifier head ----------------
__global__ void logits_kernel(const float* __restrict__ hcls, const float* __restrict__ W2,
                              const float* __restrict__ b2, float* __restrict__ out, int N)
{
    int gt = blockIdx.x * blockDim.x + threadIdx.x;
    int n = gt >> 5, lane = gt & 31;
    if (n >= N) return;
    const float* r = hcls + (size_t)n * 128;
    float x0 = r[lane], x1 = r[lane + 32], x2 = r[lane + 64], x3 = r[lane + 96];
    float s0 = x0 * W2[lane * 2]            + x1 * W2[(lane + 32) * 2]
             + x2 * W2[(lane + 64) * 2]     + x3 * W2[(lane + 96) * 2];
    float s1 = x0 * W2[lane * 2 + 1]        + x1 * W2[(lane + 32) * 2 + 1]
             + x2 * W2[(lane + 64) * 2 + 1] + x3 * W2[(lane + 96) * 2 + 1];
#pragma unroll
    for (int o = 16; o > 0; o >>= 1) {
        s0 += __shfl_xor_sync(0xffffffffu, s0, o);
        s1 += __shfl_xor_sync(0xffffffffu, s1, o);
    }
    if (lane == 0) {
        out[n * 2]     = s0 + b2[0];
        out[n * 2 + 1] = s1 + b2[1];
    }
}

// ---------------- launch ----------------
extern "C" void kernel_launch(void* const* d_in, const int* in_sizes, int n_in,
                              void* d_out, int out_size)
{
    const float* x        = (const float*)d_in[0];
    const int*   edges    = (const int*)d_in[1];
    const float* proj_W   = (const float*)d_in[2];
    const float* proj_b   = (const float*)d_in[3];
    const float* gat_W    = (const float*)d_in[4];
    const float* gat_asrc = (const float*)d_in[5];
    const float* gat_adst = (const float*)d_in[6];
    const float* gat_b    = (const float*)d_in[7];
    const float* sem_W1   = (const float*)d_in[8];
    const float* sem_b1   = (const float*)d_in[9];
    const float* sem_W2   = (const float*)d_in[10];
    const float* cls_W1   = (const float*)d_in[11];
    const float* cls_b1   = (const float*)d_in[12];
    const float* cls_W2   = (const float*)d_in[13];
    const float* cls_b2   = (const float*)d_in[14];
    float* out = (float*)d_out;

    const int N = in_sizes[0] / 128;
    const int E = in_sizes[1] / 6;

    unsigned *xH, *xL, *h0H, *h0L, *hpP, *hH, *hL, *embH, *embL, *zH, *zL, *wH, *wL;
    float *emb, *ssrc, *sdst, *tbuf, *scores, *hcls;
    int *deg, *off, *cursor, *csr, *partials;
    cudaGetSymbolAddress((void**)&xH,   g_xH);   cudaGetSymbolAddress((void**)&xL,   g_xL);
    cudaGetSymbolAddress((void**)&h0H,  g_h0H);  cudaGetSymbolAddress((void**)&h0L,  g_h0L);
    cudaGetSymbolAddress((void**)&hpP,  g_hpP);
    cudaGetSymbolAddress((void**)&hH,   g_hH);   cudaGetSymbolAddress((void**)&hL,   g_hL);
    cudaGetSymbolAddress((void**)&embH, g_embH); cudaGetSymbolAddress((void**)&embL, g_embL);
    cudaGetSymbolAddress((void**)&zH,   g_zH);   cudaGetSymbolAddress((void**)&zL,   g_zL);
    cudaGetSymbolAddress((void**)&wH,   g_wH);   cudaGetSymbolAddress((void**)&wL,   g_wL);
    cudaGetSymbolAddress((void**)&emb,  g_emb);
    cudaGetSymbolAddress((void**)&ssrc, g_ssrc); cudaGetSymbolAddress((void**)&sdst, g_sdst);
    cudaGetSymbolAddress((void**)&tbuf, g_t);
    cudaGetSymbolAddress((void**)&scores, g_scores);
    cudaGetSymbolAddress((void**)&hcls, g_hcls);
    cudaGetSymbolAddress((void**)&deg,  g_deg);  cudaGetSymbolAddress((void**)&off, g_off);
    cudaGetSymbolAddress((void**)&cursor, g_cursor);
    cudaGetSymbolAddress((void**)&csr,  g_csr);  cudaGetSymbolAddress((void**)&partials, g_partials);

    static bool s_init = false;
    static cudaStream_t st1, st2;
    static cudaEvent_t evRoot, evJ1, evJ2;
    if (!s_init) {
        cudaStreamCreateWithFlags(&st1, cudaStreamNonBlocking);
        cudaStreamCreateWithFlags(&st2, cudaStreamNonBlocking);
        cudaEventCreateWithFlags(&evRoot, cudaEventDisableTiming);
        cudaEventCreateWithFlags(&evJ1, cudaEventDisableTiming);
        cudaEventCreateWithFlags(&evJ2, cudaEventDisableTiming);
        s_init = true;
    }
    cudaStream_t streams[3] = { (cudaStream_t)0, st1, st2 };

    const int nb1024 = (N + 1023) / 1024;
    const int OFF_PROJ = 0;
    const int OFF_GAT  = 16384;
    const int OFF_SEM  = 212992;
    const int OFF_CLS  = 229376;

    // --- stream 0: weight splits, x split, proj GEMM ---
    split_pairs_kernel<<<(N * 64 + 255) / 256, 256>>>(x, xH, xL, N * 64);
    split_w_kernel<<<(64 * 256 + 255) / 256, 256>>>(proj_W, wH + OFF_PROJ, wL + OFF_PROJ, 64, 256);
    for (int i = 0; i < 6; ++i)
        split_w_kernel<<<(128 * 256 + 255) / 256, 256>>>(gat_W + (size_t)i * 65536,
            wH + OFF_GAT + i * 32768, wL + OFF_GAT + i * 32768, 128, 256);
    split_w_kernel<<<(128 * 128 + 255) / 256, 256>>>(sem_W1, wH + OFF_SEM, wL + OFF_SEM, 128, 128);
    split_w_kernel<<<(128 * 128 + 255) / 256, 256>>>(cls_W1, wH + OFF_CLS, wL + OFF_CLS, 128, 128);

    {   // h0 = x @ proj_W + proj_b -> bf16 split pairs
        dim3 grid(4, (N + 127) / 128);
        gemm_bf16_kernel<<<grid, 256>>>(xH, xL, wH + OFF_PROJ, wL + OFF_PROJ, proj_b,
                                        nullptr, h0H, h0L, nullptr,
                                        nullptr, nullptr, nullptr, nullptr, N, 256, 64, 0);
    }
    cudaEventRecord(evRoot, 0);
    cudaStreamWaitEvent(st1, evRoot, 0);
    cudaStreamWaitEvent(st2, evRoot, 0);

    // --- per-metapath pipelines on 3 streams ---
    for (int p = 0; p < 3; ++p) {
        cudaStream_t S = streams[p];
        const int* esrc = edges + (size_t)p * 2 * E;
        const int* edst = esrc + E;
        int* deg_p = deg + (size_t)p * NN;
        int* off_p = off + (size_t)p * (NN + 1);
        int* cur_p = cursor + (size_t)p * NN;
        int* csr_p = csr + (size_t)p * (EE + NN);
        int* par_p = partials + p * 64;
        unsigned* hpP_p = hpP + (size_t)p * NN * 128;
        float* ss_p = ssrc + (size_t)p * NN * 8;
        float* sd_p = sdst + (size_t)p * NN * 8;
        unsigned* hH_p = hH + (size_t)p * NN * 128;
        unsigned* hL_p = hL + (size_t)p * NN * 128;
        unsigned* eH_p = embH + (size_t)p * NN * 128;
        unsigned* eL_p = embL + (size_t)p * NN * 128;
        float* emb_p = emb + (size_t)p * NN * 256;
        float* t_p = tbuf + (size_t)p * NN * 128;

        deg_init_kernel<<<(N + 255) / 256, 256, 0, S>>>(deg_p, N);
        deg_count_kernel<<<(E + 255) / 256, 256, 0, S>>>(edst, deg_p, E);
        scan_local_kernel<<<nb1024, 1024, 0, S>>>(deg_p, off_p, par_p, N);
        scan_partials_kernel<<<1, 64, 0, S>>>(par_p, nb1024, off_p, N);
        scan_add_kernel<<<nb1024 * 4, 256, 0, S>>>(off_p, par_p, N);
        csr_init_kernel<<<(N + 255) / 256, 256, 0, S>>>(off_p, cur_p, csr_p, N);
        csr_fill_kernel<<<(E + 255) / 256, 256, 0, S>>>(esrc, edst, cur_p, csr_p, E);

        for (int l = 0; l < 2; ++l) {
            const unsigned* AHc = (l == 0) ? h0H : hH_p;
            const unsigned* ALc = (l == 0) ? h0L : hL_p;
            const unsigned* WHc = wH + OFF_GAT + (p * 2 + l) * 32768;
            const unsigned* WLc = wL + OFF_GAT + (p * 2 + l) * 32768;
            const float* as_ = gat_asrc + (size_t)(p * 2 + l) * 256;
            const float* ad_ = gat_adst + (size_t)(p * 2 + l) * 256;
            const float* bb  = gat_b    + (size_t)(p * 2 + l) * 256;

            dim3 grid(4, (N + 127) / 128);
            // GEMM -> hp (fp16) + fused s_src/s_dst
            gemm_bf16_kernel<<<grid, 256, 0, S>>>(AHc, ALc, WHc, WLc, nullptr,
                                                  nullptr, nullptr, nullptr, hpP_p,
                                                  as_, ad_, ss_p, sd_p, N, 256, 128, 0);
            if (l == 0)
                aggregate_kernel<<<(N * 32 + 255) / 256, 256, 0, S>>>(
                    off_p, csr_p, ss_p, sd_p, hpP_p, bb, nullptr, hH_p, hL_p, N);
            else
                aggregate_kernel<<<(N * 32 + 255) / 256, 256, 0, S>>>(
                    off_p, csr_p, ss_p, sd_p, hpP_p, bb, emb_p, eH_p, eL_p, N);
        }
        {
            dim3 grid(2, (N + 127) / 128);
            gemm_bf16_kernel<<<grid, 256, 0, S>>>(eH_p, eL_p, wH + OFF_SEM, wL + OFF_SEM, sem_b1,
                                                  t_p, nullptr, nullptr, nullptr,
                                                  nullptr, nullptr, nullptr, nullptr, N, 128, 128, 1);
        }
        score_kernel<<<(N * 32 + 255) / 256, 256, 0, S>>>(t_p, sem_W2, scores, N, p);
    }
    cudaEventRecord(evJ1, st1);
    cudaEventRecord(evJ2, st2);
    cudaStreamWaitEvent((cudaStream_t)0, evJ1, 0);
    cudaStreamWaitEvent((cudaStream_t)0, evJ2, 0);

    // --- join: combine + classifier ---
    combine_kernel<<<(N * 64 + 255) / 256, 256>>>(
        emb, emb + (size_t)NN * 256, emb + (size_t)2 * NN * 256, scores, zH, zL, N);
    {
        dim3 grid(2, (N + 127) / 128);
        gemm_bf16_kernel<<<grid, 256>>>(zH, zL, wH + OFF_CLS, wL + OFF_CLS, cls_b1,
                                        hcls, nullptr, nullptr, nullptr,
                                        nullptr, nullptr, nullptr, nullptr, N, 128, 128, 2);
    }
    logits_kernel<<<(N * 32 + 255) / 256, 256>>>(hcls, cls_W2, cls_b2, out, N);
}

// round 15
// speedup vs baseline: 2.6832x; 1.0236x over previous
#include <cuda_runtime.h>
#include <cuda_bf16.h>
#include <cuda_fp16.h>
#include <math.h>

#define NN 50000
#define EE 800000

// ---------------- scratch ----------------
__device__ __align__(16) unsigned g_xH[NN * 64],  g_xL[NN * 64];
__device__ __align__(16) unsigned g_h0H[NN * 128], g_h0L[NN * 128];
__device__ __align__(16) unsigned g_hpP[3ll * NN * 128];              // hp packed fp16
__device__ __align__(16) unsigned g_hH[3ll * NN * 128], g_hL[3ll * NN * 128];
__device__ __align__(16) float    g_emb[3ll * NN * 256];
__device__ __align__(16) unsigned g_embH[3ll * NN * 128], g_embL[3ll * NN * 128];
__device__ __align__(16) unsigned g_zH[NN * 128], g_zL[NN * 128];
__device__ __align__(16) float    g_ssrc[3ll * NN * 8], g_sdst[3ll * NN * 8];
__device__ __align__(16) float    g_t[3ll * NN * 128];
__device__ __align__(16) float    g_scores[NN * 3];
__device__ __align__(16) float    g_hcls[NN * 128];
__device__ __align__(16) unsigned g_wH[245760], g_wL[245760];
__device__ int g_deg[3ll * NN];
__device__ int g_off[3ll * (NN + 1)];
__device__ int g_cursor[3ll * NN];
__device__ int g_csr[3ll * (EE + NN)];
__device__ int g_partials[3 * 64];

// ---------------- helpers ----------------
__device__ __forceinline__ void split2(float a, float b, unsigned& hi, unsigned& lo)
{
    __nv_bfloat16 ah = __float2bfloat16_rn(a);
    __nv_bfloat16 bh = __float2bfloat16_rn(b);
    __nv_bfloat16 al = __float2bfloat16_rn(a - __bfloat162float(ah));
    __nv_bfloat16 bl = __float2bfloat16_rn(b - __bfloat162float(bh));
    __nv_bfloat162 h2 = __halves2bfloat162(ah, bh);
    __nv_bfloat162 l2 = __halves2bfloat162(al, bl);
    hi = *reinterpret_cast<unsigned*>(&h2);
    lo = *reinterpret_cast<unsigned*>(&l2);
}

__device__ __forceinline__ unsigned packh2(float a, float b)
{
    __half2 h = __floats2half2_rn(a, b);
    return *reinterpret_cast<unsigned*>(&h);
}

__device__ __forceinline__ float2 unpackh2(unsigned u)
{
    __half2 h = *reinterpret_cast<__half2*>(&u);
    return __half22float2(h);
}

__device__ __forceinline__ void mma_bf16(float (&d)[4], const unsigned (&a)[4], const unsigned (&b)[2])
{
    asm volatile("mma.sync.aligned.m16n8k16.row.col.f32.bf16.bf16.f32 "
        "{%0,%1,%2,%3}, {%4,%5,%6,%7}, {%8,%9}, {%0,%1,%2,%3};"
        : "+f"(d[0]), "+f"(d[1]), "+f"(d[2]), "+f"(d[3])
        : "r"(a[0]), "r"(a[1]), "r"(a[2]), "r"(a[3]), "r"(b[0]), "r"(b[1]));
}

// ---------------- split kernels ----------------
__global__ void split_pairs_kernel(const float* __restrict__ in, unsigned* __restrict__ oh,
                                   unsigned* __restrict__ ol, int npairs)
{
    int t = blockIdx.x * blockDim.x + threadIdx.x;
    if (t >= npairs) return;
    unsigned h, l;
    split2(in[2 * t], in[2 * t + 1], h, l);
    oh[t] = h; ol[t] = l;
}

__global__ void split_w_kernel(const float* __restrict__ W, unsigned* __restrict__ oh,
                               unsigned* __restrict__ ol, int K2, int N)
{
    int t = blockIdx.x * blockDim.x + threadIdx.x;
    if (t >= K2 * N) return;
    int kp = t / N, n = t - kp * N;
    unsigned h, l;
    split2(W[(size_t)(2 * kp) * N + n], W[(size_t)(2 * kp + 1) * N + n], h, l);
    oh[t] = h; ol[t] = l;
}

// ---------------- bf16x3 tensor-core GEMM, double-buffered ----------------
__global__ void gemm_bf16_kernel(const unsigned* __restrict__ AH, const unsigned* __restrict__ AL,
                                 const unsigned* __restrict__ BH, const unsigned* __restrict__ BL,
                                 const float* __restrict__ bias,
                                 float* __restrict__ outF,
                                 unsigned* __restrict__ outH, unsigned* __restrict__ outL,
                                 unsigned* __restrict__ outP,
                                 const float* __restrict__ aSrc, const float* __restrict__ aDst,
                                 float* __restrict__ sSrc, float* __restrict__ sDst,
                                 int M, int N, int K2, int act)
{
    __shared__ unsigned AsH[2][128][12], AsL[2][128][12];
    __shared__ unsigned BsH[2][64][12],  BsL[2][64][12];

    const int tid = threadIdx.x;
    const int lane = tid & 31;
    const int warp = tid >> 5;
    const int wm = warp & 3, wn = warp >> 2;
    const int rowBase = blockIdx.y * 128;
    const int colBase = blockIdx.x * 64;
    const int g = lane >> 2, t = lane & 3;

    float acc[2][4][4];
#pragma unroll
    for (int mt = 0; mt < 2; ++mt)
#pragma unroll
        for (int nt = 0; nt < 4; ++nt)
#pragma unroll
            for (int i = 0; i < 4; ++i) acc[mt][nt][i] = 0.f;

    const int am = tid >> 1;
    const int aq = (tid & 1) * 4;
    const int bn = tid & 63;
    const int bkp = tid >> 6;
    const int gr = rowBase + am;
    const bool aval = (gr < M);
    const int T = K2 >> 3;

    uint4 rAH = make_uint4(0,0,0,0), rAL = make_uint4(0,0,0,0);
    unsigned rB0, rB1, rB2, rB3;

    {
        if (aval) {
            rAH = *(const uint4*)(AH + (size_t)gr * K2 + aq);
            rAL = *(const uint4*)(AL + (size_t)gr * K2 + aq);
        }
        size_t o0 = (size_t)bkp * N + colBase + bn;
        size_t o1 = (size_t)(bkp + 4) * N + colBase + bn;
        rB0 = BH[o0]; rB1 = BL[o0]; rB2 = BH[o1]; rB3 = BL[o1];
        *(uint4*)&AsH[0][am][aq] = rAH;
        *(uint4*)&AsL[0][am][aq] = rAL;
        BsH[0][bn][bkp] = rB0;     BsL[0][bn][bkp] = rB1;
        BsH[0][bn][bkp + 4] = rB2; BsL[0][bn][bkp + 4] = rB3;
    }
    __syncthreads();

    for (int kt = 0; kt < T; ++kt) {
        const int cur = kt & 1;
        if (kt + 1 < T) {
            int kp0 = (kt + 1) * 8;
            if (aval) {
                rAH = *(const uint4*)(AH + (size_t)gr * K2 + kp0 + aq);
                rAL = *(const uint4*)(AL + (size_t)gr * K2 + kp0 + aq);
            }
            size_t o0 = (size_t)(kp0 + bkp) * N + colBase + bn;
            size_t o1 = (size_t)(kp0 + bkp + 4) * N + colBase + bn;
            rB0 = BH[o0]; rB1 = BL[o0]; rB2 = BH[o1]; rB3 = BL[o1];
        }

        unsigned aH[2][4], aL[2][4], bH[4][2], bL[4][2];
#pragma unroll
        for (int mt = 0; mt < 2; ++mt) {
            int mr = wm * 32 + mt * 16;
            aH[mt][0] = AsH[cur][mr + g][t];     aH[mt][1] = AsH[cur][mr + 8 + g][t];
            aH[mt][2] = AsH[cur][mr + g][t + 4]; aH[mt][3] = AsH[cur][mr + 8 + g][t + 4];
            aL[mt][0] = AsL[cur][mr + g][t];     aL[mt][1] = AsL[cur][mr + 8 + g][t];
            aL[mt][2] = AsL[cur][mr + g][t + 4]; aL[mt][3] = AsL[cur][mr + 8 + g][t + 4];
        }
#pragma unroll
        for (int nt = 0; nt < 4; ++nt) {
            int nr = wn * 32 + nt * 8;
            bH[nt][0] = BsH[cur][nr + g][t]; bH[nt][1] = BsH[cur][nr + g][t + 4];
            bL[nt][0] = BsL[cur][nr + g][t]; bL[nt][1] = BsL[cur][nr + g][t + 4];
        }
#pragma unroll
        for (int mt = 0; mt < 2; ++mt)
#pragma unroll
            for (int nt = 0; nt < 4; ++nt) {
                mma_bf16(acc[mt][nt], aH[mt], bH[nt]);
                mma_bf16(acc[mt][nt], aL[mt], bH[nt]);
                mma_bf16(acc[mt][nt], aH[mt], bL[nt]);
            }

        if (kt + 1 < T) {
            const int nxt = 1 - cur;
            *(uint4*)&AsH[nxt][am][aq] = rAH;
            *(uint4*)&AsL[nxt][am][aq] = rAL;
            BsH[nxt][bn][bkp] = rB0;     BsL[nxt][bn][bkp] = rB1;
            BsH[nxt][bn][bkp + 4] = rB2; BsL[nxt][bn][bkp + 4] = rB3;
            __syncthreads();
        }
    }

    float pS[2][2] = {{0.f, 0.f}, {0.f, 0.f}};
    float pD[2][2] = {{0.f, 0.f}, {0.f, 0.f}};
    const bool doS = (aSrc != nullptr);

#pragma unroll
    for (int mt = 0; mt < 2; ++mt) {
#pragma unroll
        for (int nt = 0; nt < 4; ++nt) {
            int c = colBase + wn * 32 + nt * 8 + 2 * t;
            float b0 = bias ? bias[c] : 0.f;
            float b1 = bias ? bias[c + 1] : 0.f;
#pragma unroll
            for (int half = 0; half < 2; ++half) {
                int r = rowBase + wm * 32 + mt * 16 + g + half * 8;
                float v0 = acc[mt][nt][half * 2 + 0] + b0;
                float v1 = acc[mt][nt][half * 2 + 1] + b1;
                if (act == 1) { v0 = tanhf(v0); v1 = tanhf(v1); }
                else if (act == 2) { v0 = fmaxf(v0, 0.f); v1 = fmaxf(v1, 0.f); }
                if (doS) {
                    pS[mt][half] += v0 * aSrc[c] + v1 * aSrc[c + 1];
                    pD[mt][half] += v0 * aDst[c] + v1 * aDst[c + 1];
                }
                if (r < M) {
                    if (outF) *(float2*)(outF + (size_t)r * N + c) = make_float2(v0, v1);
                    if (outP) outP[(size_t)r * (N >> 1) + (c >> 1)] = packh2(v0, v1);
                    if (outH) {
                        unsigned h, l;
                        split2(v0, v1, h, l);
                        size_t oi = (size_t)r * (N >> 1) + (c >> 1);
                        outH[oi] = h; outL[oi] = l;
                    }
                }
            }
        }
    }
    if (doS) {
        int head = blockIdx.x * 2 + wn;
#pragma unroll
        for (int mt = 0; mt < 2; ++mt)
#pragma unroll
            for (int half = 0; half < 2; ++half) {
                float s = pS[mt][half], d = pD[mt][half];
                s += __shfl_xor_sync(0xffffffffu, s, 1);
                s += __shfl_xor_sync(0xffffffffu, s, 2);
                d += __shfl_xor_sync(0xffffffffu, d, 1);
                d += __shfl_xor_sync(0xffffffffu, d, 2);
                int r = rowBase + wm * 32 + mt * 16 + g + half * 8;
                if (t == 0 && r < M) {
                    sSrc[r * 8 + head] = s;
                    sDst[r * 8 + head] = d;
                }
            }
    }
}

// ---------------- CSR build ----------------
__global__ void deg_init_kernel(int* __restrict__ deg, int N)
{
    int t = blockIdx.x * blockDim.x + threadIdx.x;
    if (t < N) deg[t] = 1;
}

__global__ void deg_count_kernel(const int* __restrict__ edst, int* __restrict__ deg, int E)
{
    int t = blockIdx.x * blockDim.x + threadIdx.x;
    if (t < E) atomicAdd(deg + __ldg(edst + t), 1);
}

__global__ void scan_local_kernel(const int* __restrict__ deg, int* __restrict__ off,
                                  int* __restrict__ partials, int N)
{
    __shared__ int sm[1024];
    int b = blockIdx.x, tid = threadIdx.x;
    int i = b * 1024 + tid;
    int v = (i < N) ? deg[i] : 0;
    sm[tid] = v;
    __syncthreads();
    for (int o = 1; o < 1024; o <<= 1) {
        int x = (tid >= o) ? sm[tid - o] : 0;
        __syncthreads();
        sm[tid] += x;
        __syncthreads();
    }
    if (i < N) off[i] = sm[tid] - v;
    if (tid == 1023) partials[b] = sm[1023];
}

__global__ void scan_partials_kernel(int* __restrict__ partials, int nb,
                                     int* __restrict__ off, int N)
{
    __shared__ int sm[64];
    int tid = threadIdx.x;
    int v = (tid < nb) ? partials[tid] : 0;
    sm[tid] = v;
    __syncthreads();
    for (int o = 1; o < 64; o <<= 1) {
        int x = (tid >= o) ? sm[tid - o] : 0;
        __syncthreads();
        sm[tid] += x;
        __syncthreads();
    }
    if (tid < nb) partials[tid] = sm[tid] - v;
    if (tid == 63) off[N] = sm[63];
}

__global__ void scan_add_kernel(int* __restrict__ off, const int* __restrict__ partials, int N)
{
    int i = blockIdx.x * blockDim.x + threadIdx.x;
    if (i < N) off[i] += partials[blockIdx.x >> 2];
}

__global__ void csr_init_kernel(const int* __restrict__ off, int* __restrict__ cursor,
                                int* __restrict__ csr, int N)
{
    int t = blockIdx.x * blockDim.x + threadIdx.x;
    if (t >= N) return;
    int o = off[t];
    csr[o] = t;
    cursor[t] = o + 1;
}

__global__ void csr_fill_kernel(const int* __restrict__ esrc, const int* __restrict__ edst,
                                int* __restrict__ cursor, int* __restrict__ csr, int E)
{
    int t = blockIdx.x * blockDim.x + threadIdx.x;
    if (t >= E) return;
    int d = __ldg(edst + t);
    int pos = atomicAdd(cursor + d, 1);
    csr[pos] = __ldg(esrc + t);
}

// ---------------- warp-per-node gather aggregation (fp16 hp, unroll-8) ----------------
__global__ void aggregate_kernel(const int* __restrict__ off, const int* __restrict__ csr,
                                 const float* __restrict__ s_src, const float* __restrict__ s_dst,
                                 const unsigned* __restrict__ hpP, const float* __restrict__ bias,
                                 float* __restrict__ outF,
                                 unsigned* __restrict__ outH, unsigned* __restrict__ outL, int N)
{
    int gt = blockIdx.x * blockDim.x + threadIdx.x;
    int w = gt >> 5, lane = gt & 31;
    if (w >= N) return;
    int beg = __ldg(off + w), end = __ldg(off + w + 1);
    int h = lane >> 2;
    float sd = __ldg(s_dst + w * 8 + h);

    float acc[8];
#pragma unroll
    for (int i = 0; i < 8; ++i) acc[i] = 0.f;
    float den = 0.f;

    int e = beg;
    for (; e + 8 <= end; e += 8) {
        int s[8];
#pragma unroll
        for (int i = 0; i < 8; ++i) s[i] = __ldg(csr + e + i);
        float l[8];
        uint4 q[8];
#pragma unroll
        for (int i = 0; i < 8; ++i) l[i] = __ldg(s_src + s[i] * 8 + h);
#pragma unroll
        for (int i = 0; i < 8; ++i) q[i] = __ldg((const uint4*)(hpP + (size_t)s[i] * 128) + lane);
        float xv[8];
#pragma unroll
        for (int i = 0; i < 8; ++i) {
            float ee = l[i] + sd;
            ee = (ee > 0.f) ? ee : 0.2f * ee;
            xv[i] = __expf(ee);
            den += xv[i];
        }
#pragma unroll
        for (int j = 0; j < 4; ++j) {
#pragma unroll
            for (int i = 0; i < 8; ++i) {
                float2 f = unpackh2(((const unsigned*)&q[i])[j]);
                acc[2 * j]     += xv[i] * f.x;
                acc[2 * j + 1] += xv[i] * f.y;
            }
        }
    }
    for (; e + 4 <= end; e += 4) {
        int s0 = __ldg(csr + e),     s1 = __ldg(csr + e + 1);
        int s2 = __ldg(csr + e + 2), s3 = __ldg(csr + e + 3);
        float l0 = __ldg(s_src + s0 * 8 + h), l1 = __ldg(s_src + s1 * 8 + h);
        float l2 = __ldg(s_src + s2 * 8 + h), l3 = __ldg(s_src + s3 * 8 + h);
        uint4 q0 = __ldg((const uint4*)(hpP + (size_t)s0 * 128) + lane);
        uint4 q1 = __ldg((const uint4*)(hpP + (size_t)s1 * 128) + lane);
        uint4 q2 = __ldg((const uint4*)(hpP + (size_t)s2 * 128) + lane);
        uint4 q3 = __ldg((const uint4*)(hpP + (size_t)s3 * 128) + lane);
        l0 += sd; l0 = (l0 > 0.f) ? l0 : 0.2f * l0;
        l1 += sd; l1 = (l1 > 0.f) ? l1 : 0.2f * l1;
        l2 += sd; l2 = (l2 > 0.f) ? l2 : 0.2f * l2;
        l3 += sd; l3 = (l3 > 0.f) ? l3 : 0.2f * l3;
        float x0 = __expf(l0), x1 = __expf(l1), x2 = __expf(l2), x3 = __expf(l3);
        den += (x0 + x1) + (x2 + x3);
#pragma unroll
        for (int j = 0; j < 4; ++j) {
            float2 f0 = unpackh2(((const unsigned*)&q0)[j]);
            float2 f1 = unpackh2(((const unsigned*)&q1)[j]);
            float2 f2 = unpackh2(((const unsigned*)&q2)[j]);
            float2 f3 = unpackh2(((const unsigned*)&q3)[j]);
            acc[2 * j]     += x0 * f0.x + x1 * f1.x + x2 * f2.x + x3 * f3.x;
            acc[2 * j + 1] += x0 * f0.y + x1 * f1.y + x2 * f2.y + x3 * f3.y;
        }
    }
    for (; e < end; ++e) {
        int s = __ldg(csr + e);
        float ee = __ldg(s_src + s * 8 + h) + sd;
        ee = (ee > 0.f) ? ee : 0.2f * ee;
        float ex = __expf(ee);
        den += ex;
        uint4 q = __ldg((const uint4*)(hpP + (size_t)s * 128) + lane);
#pragma unroll
        for (int j = 0; j < 4; ++j) {
            float2 f = unpackh2(((const unsigned*)&q)[j]);
            acc[2 * j]     += ex * f.x;
            acc[2 * j + 1] += ex * f.y;
        }
    }
    float inv = 1.f / den;
    const float4* bb = (const float4*)(bias + lane * 8);
    float4 b0 = bb[0], b1 = bb[1];
    float o[8] = { acc[0] * inv + b0.x, acc[1] * inv + b0.y, acc[2] * inv + b0.z, acc[3] * inv + b0.w,
                   acc[4] * inv + b1.x, acc[5] * inv + b1.y, acc[6] * inv + b1.z, acc[7] * inv + b1.w };
#pragma unroll
    for (int i = 0; i < 8; ++i) o[i] = (o[i] > 0.f) ? o[i] : expm1f(o[i]);  // elu
    if (outF) {
        float4* ov = (float4*)(outF + (size_t)w * 256 + lane * 8);
        ov[0] = make_float4(o[0], o[1], o[2], o[3]);
        ov[1] = make_float4(o[4], o[5], o[6], o[7]);
    }
#pragma unroll
    for (int j = 0; j < 4; ++j) {
        unsigned hh, ll;
        split2(o[2 * j], o[2 * j + 1], hh, ll);
        size_t oi = (size_t)w * 128 + lane * 4 + j;
        outH[oi] = hh; outL[oi] = ll;
    }
}

// ---------------- semantic score ----------------
__global__ void score_kernel(const float* __restrict__ t128, const float* __restrict__ W2,
                             float* __restrict__ scores, int N, int p)
{
    int gt = blockIdx.x * blockDim.x + threadIdx.x;
    int n = gt >> 5, lane = gt & 31;
    if (n >= N) return;
    const float* r = t128 + (size_t)n * 128;
    float v = r[lane] * W2[lane] + r[lane + 32] * W2[lane + 32]
            + r[lane + 64] * W2[lane + 64] + r[lane + 96] * W2[lane + 96];
#pragma unroll
    for (int o = 16; o > 0; o >>= 1) v += __shfl_xor_sync(0xffffffffu, v, o);
    if (lane == 0) scores[n * 3 + p] = v;
}

// ---------------- softmax over 3 metapaths + weighted sum ----------------
__global__ void combine_kernel(const float* __restrict__ e0, const float* __restrict__ e1,
                               const float* __restrict__ e2, const float* __restrict__ scores,
                               unsigned* __restrict__ zH, unsigned* __restrict__ zL, int N)
{
    int t = blockIdx.x * blockDim.x + threadIdx.x;
    if (t >= N * 64) return;
    int n = t >> 6, q = t & 63;
    float s0 = scores[n * 3], s1 = scores[n * 3 + 1], s2 = scores[n * 3 + 2];
    float m = fmaxf(s0, fmaxf(s1, s2));
    float w0 = __expf(s0 - m), w1 = __expf(s1 - m), w2 = __expf(s2 - m);
    float inv = 1.f / (w0 + w1 + w2);
    w0 *= inv; w1 *= inv; w2 *= inv;
    size_t offi = (size_t)n * 256 + q * 4;
    float4 a = *(const float4*)(e0 + offi);
    float4 b = *(const float4*)(e1 + offi);
    float4 c = *(const float4*)(e2 + offi);
    float ox = w0 * a.x + w1 * b.x + w2 * c.x;
    float oy = w0 * a.y + w1 * b.y + w2 * c.y;
    float oz = w0 * a.z + w1 * b.z + w2 * c.z;
    float ow = w0 * a.w + w1 * b.w + w2 * c.w;
    unsigned h, l;
    size_t zi = (size_t)n * 128 + q * 2;
    split2(ox, oy, h, l); zH[zi] = h;     zL[zi] = l;
    split2(oz, ow, h, l); zH[zi + 1] = h; zL[zi + 1] = l;
}

// ---------------- classifier head ----------------
__global__ void logits_kernel(const float* __restrict__ hcls, const float* __restrict__ W2,
                              const float* __restrict__ b2, float* __restrict__ out, int N)
{
    int gt = blockIdx.x * blockDim.x + threadIdx.x;
    int n = gt >> 5, lane = gt & 31;
    if (n >= N) return;
    const float* r = hcls + (size_t)n * 128;
    float x0 = r[lane], x1 = r[lane + 32], x2 = r[lane + 64], x3 = r[lane + 96];
    float s0 = x0 * W2[lane * 2]            + x1 * W2[(lane + 32) * 2]
             + x2 * W2[(lane + 64) * 2]     + x3 * W2[(lane + 96) * 2];
    float s1 = x0 * W2[lane * 2 + 1]        + x1 * W2[(lane + 32) * 2 + 1]
             + x2 * W2[(lane + 64) * 2 + 1] + x3 * W2[(lane + 96) * 2 + 1];
#pragma unroll
    for (int o = 16; o > 0; o >>= 1) {
        s0 += __shfl_xor_sync(0xffffffffu, s0, o);
        s1 += __shfl_xor_sync(0xffffffffu, s1, o);
    }
    if (lane == 0) {
        out[n * 2]     = s0 + b2[0];
        out[n * 2 + 1] = s1 + b2[1];
    }
}

// ---------------- launch ----------------
extern "C" void kernel_launch(void* const* d_in, const int* in_sizes, int n_in,
                              void* d_out, int out_size)
{
    const float* x        = (const float*)d_in[0];
    const int*   edges    = (const int*)d_in[1];
    const float* proj_W   = (const float*)d_in[2];
    const float* proj_b   = (const float*)d_in[3];
    const float* gat_W    = (const float*)d_in[4];
    const float* gat_asrc = (const float*)d_in[5];
    const float* gat_adst = (const float*)d_in[6];
    const float* gat_b    = (const float*)d_in[7];
    const float* sem_W1   = (const float*)d_in[8];
    const float* sem_b1   = (const float*)d_in[9];
    const float* sem_W2   = (const float*)d_in[10];
    const float* cls_W1   = (const float*)d_in[11];
    const float* cls_b1   = (const float*)d_in[12];
    const float* cls_W2   = (const float*)d_in[13];
    const float* cls_b2   = (const float*)d_in[14];
    float* out = (float*)d_out;

    const int N = in_sizes[0] / 128;
    const int E = in_sizes[1] / 6;

    unsigned *xH, *xL, *h0H, *h0L, *hpP, *hH, *hL, *embH, *embL, *zH, *zL, *wH, *wL;
    float *emb, *ssrc, *sdst, *tbuf, *scores, *hcls;
    int *deg, *off, *cursor, *csr, *partials;
    cudaGetSymbolAddress((void**)&xH,   g_xH);   cudaGetSymbolAddress((void**)&xL,   g_xL);
    cudaGetSymbolAddress((void**)&h0H,  g_h0H);  cudaGetSymbolAddress((void**)&h0L,  g_h0L);
    cudaGetSymbolAddress((void**)&hpP,  g_hpP);
    cudaGetSymbolAddress((void**)&hH,   g_hH);   cudaGetSymbolAddress((void**)&hL,   g_hL);
    cudaGetSymbolAddress((void**)&embH, g_embH); cudaGetSymbolAddress((void**)&embL, g_embL);
    cudaGetSymbolAddress((void**)&zH,   g_zH);   cudaGetSymbolAddress((void**)&zL,   g_zL);
    cudaGetSymbolAddress((void**)&wH,   g_wH);   cudaGetSymbolAddress((void**)&wL,   g_wL);
    cudaGetSymbolAddress((void**)&emb,  g_emb);
    cudaGetSymbolAddress((void**)&ssrc, g_ssrc); cudaGetSymbolAddress((void**)&sdst, g_sdst);
    cudaGetSymbolAddress((void**)&tbuf, g_t);
    cudaGetSymbolAddress((void**)&scores, g_scores);
    cudaGetSymbolAddress((void**)&hcls, g_hcls);
    cudaGetSymbolAddress((void**)&deg,  g_deg);  cudaGetSymbolAddress((void**)&off, g_off);
    cudaGetSymbolAddress((void**)&cursor, g_cursor);
    cudaGetSymbolAddress((void**)&csr,  g_csr);  cudaGetSymbolAddress((void**)&partials, g_partials);

    static bool s_init = false;
    static cudaStream_t st1, st2, st3;
    static cudaEvent_t evStart, evRoot, evC0, evJ1, evJ2;
    if (!s_init) {
        cudaStreamCreateWithFlags(&st1, cudaStreamNonBlocking);
        cudaStreamCreateWithFlags(&st2, cudaStreamNonBlocking);
        cudaStreamCreateWithFlags(&st3, cudaStreamNonBlocking);
        cudaEventCreateWithFlags(&evStart, cudaEventDisableTiming);
        cudaEventCreateWithFlags(&evRoot, cudaEventDisableTiming);
        cudaEventCreateWithFlags(&evC0, cudaEventDisableTiming);
        cudaEventCreateWithFlags(&evJ1, cudaEventDisableTiming);
        cudaEventCreateWithFlags(&evJ2, cudaEventDisableTiming);
        s_init = true;
    }
    cudaStream_t streams[3] = { (cudaStream_t)0, st1, st2 };
    cudaStream_t csrStreams[3] = { st3, st1, st2 };

    const int nb1024 = (N + 1023) / 1024;
    const int OFF_PROJ = 0;
    const int OFF_GAT  = 16384;
    const int OFF_SEM  = 212992;
    const int OFF_CLS  = 229376;

    // --- fork: CSR builds run on st3/st1/st2 concurrently with splits+proj ---
    cudaEventRecord(evStart, 0);
    cudaStreamWaitEvent(st1, evStart, 0);
    cudaStreamWaitEvent(st2, evStart, 0);
    cudaStreamWaitEvent(st3, evStart, 0);
    for (int p = 0; p < 3; ++p) {
        cudaStream_t S = csrStreams[p];
        const int* esrc = edges + (size_t)p * 2 * E;
        const int* edst = esrc + E;
        int* deg_p = deg + (size_t)p * NN;
        int* off_p = off + (size_t)p * (NN + 1);
        int* cur_p = cursor + (size_t)p * NN;
        int* csr_p = csr + (size_t)p * (EE + NN);
        int* par_p = partials + p * 64;
        deg_init_kernel<<<(N + 255) / 256, 256, 0, S>>>(deg_p, N);
        deg_count_kernel<<<(E + 255) / 256, 256, 0, S>>>(edst, deg_p, E);
        scan_local_kernel<<<nb1024, 1024, 0, S>>>(deg_p, off_p, par_p, N);
        scan_partials_kernel<<<1, 64, 0, S>>>(par_p, nb1024, off_p, N);
        scan_add_kernel<<<nb1024 * 4, 256, 0, S>>>(off_p, par_p, N);
        csr_init_kernel<<<(N + 255) / 256, 256, 0, S>>>(off_p, cur_p, csr_p, N);
        csr_fill_kernel<<<(E + 255) / 256, 256, 0, S>>>(esrc, edst, cur_p, csr_p, E);
    }
    cudaEventRecord(evC0, st3);

    // --- stream 0: weight splits, x split, proj GEMM ---
    split_pairs_kernel<<<(N * 64 + 255) / 256, 256>>>(x, xH, xL, N * 64);
    split_w_kernel<<<(64 * 256 + 255) / 256, 256>>>(proj_W, wH + OFF_PROJ, wL + OFF_PROJ, 64, 256);
    for (int i = 0; i < 6; ++i)
        split_w_kernel<<<(128 * 256 + 255) / 256, 256>>>(gat_W + (size_t)i * 65536,
            wH + OFF_GAT + i * 32768, wL + OFF_GAT + i * 32768, 128, 256);
    split_w_kernel<<<(128 * 128 + 255) / 256, 256>>>(sem_W1, wH + OFF_SEM, wL + OFF_SEM, 128, 128);
    split_w_kernel<<<(128 * 128 + 255) / 256, 256>>>(cls_W1, wH + OFF_CLS, wL + OFF_CLS, 128, 128);

    {
        dim3 grid(4, (N + 127) / 128);
        gemm_bf16_kernel<<<grid, 256>>>(xH, xL, wH + OFF_PROJ, wL + OFF_PROJ, proj_b,
                                        nullptr, h0H, h0L, nullptr,
                                        nullptr, nullptr, nullptr, nullptr, N, 256, 64, 0);
    }
    cudaEventRecord(evRoot, 0);
    cudaStreamWaitEvent(st1, evRoot, 0);
    cudaStreamWaitEvent(st2, evRoot, 0);
    cudaStreamWaitEvent((cudaStream_t)0, evC0, 0);  // p0 aggregate needs CSR from st3

    // --- per-metapath GEMM/aggregate pipelines ---
    for (int p = 0; p < 3; ++p) {
        cudaStream_t S = streams[p];
        int* off_p = off + (size_t)p * (NN + 1);
        int* csr_p = csr + (size_t)p * (EE + NN);
        unsigned* hpP_p = hpP + (size_t)p * NN * 128;
        float* ss_p = ssrc + (size_t)p * NN * 8;
        float* sd_p = sdst + (size_t)p * NN * 8;
        unsigned* hH_p = hH + (size_t)p * NN * 128;
        unsigned* hL_p = hL + (size_t)p * NN * 128;
        unsigned* eH_p = embH + (size_t)p * NN * 128;
        unsigned* eL_p = embL + (size_t)p * NN * 128;
        float* emb_p = emb + (size_t)p * NN * 256;
        float* t_p = tbuf + (size_t)p * NN * 128;

        for (int l = 0; l < 2; ++l) {
            const unsigned* AHc = (l == 0) ? h0H : hH_p;
            const unsigned* ALc = (l == 0) ? h0L : hL_p;
            const unsigned* WHc = wH + OFF_GAT + (p * 2 + l) * 32768;
            const unsigned* WLc = wL + OFF_GAT + (p * 2 + l) * 32768;
            const float* as_ = gat_asrc + (size_t)(p * 2 + l) * 256;
            const float* ad_ = gat_adst + (size_t)(p * 2 + l) * 256;
            const float* bb  = gat_b    + (size_t)(p * 2 + l) * 256;

            dim3 grid(4, (N + 127) / 128);
            gemm_bf16_kernel<<<grid, 256, 0, S>>>(AHc, ALc, WHc, WLc, nullptr,
                                                  nullptr, nullptr, nullptr, hpP_p,
                                                  as_, ad_, ss_p, sd_p, N, 256, 128, 0);
            if (l == 0)
                aggregate_kernel<<<(N * 32 + 255) / 256, 256, 0, S>>>(
                    off_p, csr_p, ss_p, sd_p, hpP_p, bb, nullptr, hH_p, hL_p, N);
            else
                aggregate_kernel<<<(N * 32 + 255) / 256, 256, 0, S>>>(
                    off_p, csr_p, ss_p, sd_p, hpP_p, bb, emb_p, eH_p, eL_p, N);
        }
        {
            dim3 grid(2, (N + 127) / 128);
            gemm_bf16_kernel<<<grid, 256, 0, S>>>(eH_p, eL_p, wH + OFF_SEM, wL + OFF_SEM, sem_b1,
                                                  t_p, nullptr, nullptr, nullptr,
                                                  nullptr, nullptr, nullptr, nullptr, N, 128, 128, 1);
        }
        score_kernel<<<(N * 32 + 255) / 256, 256, 0, S>>>(t_p, sem_W2, scores, N, p);
    }
    cudaEventRecord(evJ1, st1);
    cudaEventRecord(evJ2, st2);
    cudaStreamWaitEvent((cudaStream_t)0, evJ1, 0);
    cudaStreamWaitEvent((cudaStream_t)0, evJ2, 0);

    // --- join: combine + classifier ---
    combine_kernel<<<(N * 64 + 255) / 256, 256>>>(
        emb, emb + (size_t)NN * 256, emb + (size_t)2 * NN * 256, scores, zH, zL, N);
    {
        dim3 grid(2, (N + 127) / 128);
        gemm_bf16_kernel<<<grid, 256>>>(zH, zL, wH + OFF_CLS, wL + OFF_CLS, cls_b1,
                                        hcls, nullptr, nullptr, nullptr,
                                        nullptr, nullptr, nullptr, nullptr, N, 128, 128, 2);
    }
    logits_kernel<<<(N * 32 + 255) / 256, 256>>>(hcls, cls_W2, cls_b2, out, N);
}